// round 1
// baseline (speedup 1.0000x reference)
#include <cuda_runtime.h>
#include <cuda_bf16.h>
#include <cstddef>

// Problem constants
// B_ = 256 (NW*B), N = 128, C = 768, H = 12, hd = 64, NW = 64
#define B_TOT   256
#define SEQ     128
#define CDIM    768
#define HEADS   12
#define HD      64
#define NW      64
#define TOKENS  (B_TOT * SEQ)          // 32768
#define QKVDIM  (3 * CDIM)             // 2304

// Scratch (allocation-free rule: __device__ globals)
__device__ float g_qkv[(size_t)TOKENS * QKVDIM];   // (token, [3,H,hd]) ~302MB
__device__ float g_att[(size_t)TOKENS * CDIM];     // (token, h*64+d)  ~100MB

// ---------------------------------------------------------------------------
// SGEMM: C[M,N] = A[M,K] @ W[N,K]^T (+ bias). Both A and W row-major, K contig.
// BM=BN=128, BK=8, 256 threads, 8x8 register tile.
// ---------------------------------------------------------------------------
template<bool ADD_BIAS>
__global__ __launch_bounds__(256)
void sgemm_abT(const float* __restrict__ A, const float* __restrict__ W,
               const float* __restrict__ bias, float* __restrict__ C,
               int M, int N, int K) {
    constexpr int BM = 128, BN = 128, BK = 8;
    __shared__ float As[BK][BM];
    __shared__ float Ws[BK][BN];
    const int tid = threadIdx.x;
    const int bm = blockIdx.y * BM;
    const int bn = blockIdx.x * BN;
    const int ty = tid >> 4;          // 0..15
    const int tx = tid & 15;          // 0..15
    const int lrow = tid >> 1;        // 0..127
    const int lk = (tid & 1) * 4;     // 0 or 4

    const float* Aread = A + (size_t)(bm + lrow) * K + lk;
    const float* Wread = W + (size_t)(bn + lrow) * K + lk;

    float acc[8][8] = {};
    for (int k0 = 0; k0 < K; k0 += BK) {
        float4 a4 = *(const float4*)(Aread + k0);
        float4 w4 = *(const float4*)(Wread + k0);
        As[lk + 0][lrow] = a4.x; As[lk + 1][lrow] = a4.y;
        As[lk + 2][lrow] = a4.z; As[lk + 3][lrow] = a4.w;
        Ws[lk + 0][lrow] = w4.x; Ws[lk + 1][lrow] = w4.y;
        Ws[lk + 2][lrow] = w4.z; Ws[lk + 3][lrow] = w4.w;
        __syncthreads();
        #pragma unroll
        for (int kk = 0; kk < BK; kk++) {
            float a[8], b[8];
            #pragma unroll
            for (int i = 0; i < 8; i++) a[i] = As[kk][ty * 8 + i];
            #pragma unroll
            for (int j = 0; j < 8; j++) b[j] = Ws[kk][tx * 8 + j];
            #pragma unroll
            for (int i = 0; i < 8; i++)
                #pragma unroll
                for (int j = 0; j < 8; j++)
                    acc[i][j] += a[i] * b[j];
        }
        __syncthreads();
    }
    #pragma unroll
    for (int i = 0; i < 8; i++) {
        size_t row = (size_t)(bm + ty * 8 + i);
        #pragma unroll
        for (int j = 0; j < 8; j += 4) {
            int col = bn + tx * 8 + j;
            float4 r;
            r.x = acc[i][j + 0]; r.y = acc[i][j + 1];
            r.z = acc[i][j + 2]; r.w = acc[i][j + 3];
            if (ADD_BIAS) {
                r.x += bias[col + 0]; r.y += bias[col + 1];
                r.z += bias[col + 2]; r.w += bias[col + 3];
            }
            *(float4*)(C + row * N + col) = r;
        }
    }
}

// ---------------------------------------------------------------------------
// Fused window attention: one block per (b, h). 512 threads.
// SMEM: q[128][64], ktmp[128][65], kT[64][128], v[128][68], S[128][132], bias[256]
// = 50560 floats = 202240 bytes (dynamic).
// ---------------------------------------------------------------------------
#define ATTN_SMEM_FLOATS 50560
#define ATTN_SMEM_BYTES  (ATTN_SMEM_FLOATS * 4)

__global__ __launch_bounds__(512)
void attn_kernel(const float* __restrict__ qkv, const float* __restrict__ mask,
                 const float* __restrict__ bias_table, float* __restrict__ att) {
    extern __shared__ float sm[];
    float* sq    = sm;            // [128][64]   : 8192
    float* sktmp = sm + 8192;     // [128][65]   : 8320
    float* skT   = sm + 16512;    // [64][128]   : 8192
    float* sv    = sm + 24704;    // [128][68]   : 8704
    float* sS    = sm + 33408;    // [128][132]  : 16896
    float* sbias = sm + 50304;    // [255]

    const int tid = threadIdx.x;
    const int b = blockIdx.x / HEADS;
    const int h = blockIdx.x % HEADS;
    const int w = b & (NW - 1);

    const float* base = qkv + (size_t)b * SEQ * QKVDIM + h * HD;

    // Load q (pre-scaled), k, v — coalesced along d
    for (int idx = tid; idx < SEQ * HD; idx += 512) {
        int n = idx >> 6, d = idx & 63;
        const float* p = base + (size_t)n * QKVDIM + d;
        sq[n * 64 + d]    = p[0] * 0.125f;     // hd^-0.5
        sktmp[n * 65 + d] = p[CDIM];
        sv[n * 68 + d]    = p[2 * CDIM];
    }
    if (tid < 2 * SEQ - 1) sbias[tid] = bias_table[tid * HEADS + h];
    __syncthreads();

    // Transpose k -> kT[d][n] (conflict-free both sides: 65 odd / 128 with n lanes)
    for (int idx = tid; idx < SEQ * HD; idx += 512) {
        int n = idx & 127, d = idx >> 7;
        skT[d * 128 + n] = sktmp[n * 65 + d];
    }
    __syncthreads();

    // S = (q*scale) @ k^T + rel_bias + window_mask, register-tiled 8x4
    {
        const int trow = tid >> 5;     // 0..15 -> rows trow*8
        const int tcol = tid & 31;     // 0..31 -> cols tcol*4
        const int i0 = trow * 8, j0 = tcol * 4;
        float acc[8][4] = {};
        #pragma unroll 8
        for (int d = 0; d < 64; d++) {
            float4 b4 = *(const float4*)(skT + d * 128 + j0);
            #pragma unroll
            for (int i = 0; i < 8; i++) {
                float a = sq[(i0 + i) * 64 + d];
                acc[i][0] += a * b4.x; acc[i][1] += a * b4.y;
                acc[i][2] += a * b4.z; acc[i][3] += a * b4.w;
            }
        }
        const float4* m4 = (const float4*)(mask + (size_t)w * SEQ * SEQ);
        #pragma unroll
        for (int i = 0; i < 8; i++) {
            int ii = i0 + i;
            float4 mm = m4[(ii * SEQ + j0) >> 2];
            float4 r;
            r.x = acc[i][0] + sbias[ii - (j0 + 0) + SEQ - 1] + mm.x;
            r.y = acc[i][1] + sbias[ii - (j0 + 1) + SEQ - 1] + mm.y;
            r.z = acc[i][2] + sbias[ii - (j0 + 2) + SEQ - 1] + mm.z;
            r.w = acc[i][3] + sbias[ii - (j0 + 3) + SEQ - 1] + mm.w;
            *(float4*)(sS + ii * 132 + j0) = r;
        }
    }
    __syncthreads();

    // Row softmax: 16 warps, each warp owns rows wid, wid+16, ...
    {
        const int wid = tid >> 5, lane = tid & 31;
        for (int r = wid; r < SEQ; r += 16) {
            float* row = sS + r * 132;
            float v0 = row[lane], v1 = row[lane + 32];
            float v2 = row[lane + 64], v3 = row[lane + 96];
            float mx = fmaxf(fmaxf(v0, v1), fmaxf(v2, v3));
            #pragma unroll
            for (int o = 16; o; o >>= 1) mx = fmaxf(mx, __shfl_xor_sync(0xffffffffu, mx, o));
            v0 = __expf(v0 - mx); v1 = __expf(v1 - mx);
            v2 = __expf(v2 - mx); v3 = __expf(v3 - mx);
            float s = v0 + v1 + v2 + v3;
            #pragma unroll
            for (int o = 16; o; o >>= 1) s += __shfl_xor_sync(0xffffffffu, s, o);
            float inv = 1.0f / s;
            row[lane] = v0 * inv; row[lane + 32] = v1 * inv;
            row[lane + 64] = v2 * inv; row[lane + 96] = v3 * inv;
        }
    }
    __syncthreads();

    // out = P @ V, register-tiled 4x4
    {
        const int trow = tid >> 4;     // 0..31 -> rows trow*4
        const int tcol = tid & 15;     // 0..15 -> cols tcol*4
        const int r0 = trow * 4, c0 = tcol * 4;
        float acc[4][4] = {};
        #pragma unroll 8
        for (int m = 0; m < SEQ; m++) {
            float4 b4 = *(const float4*)(sv + m * 68 + c0);
            #pragma unroll
            for (int i = 0; i < 4; i++) {
                float a = sS[(r0 + i) * 132 + m];
                acc[i][0] += a * b4.x; acc[i][1] += a * b4.y;
                acc[i][2] += a * b4.z; acc[i][3] += a * b4.w;
            }
        }
        float* obase = att + (size_t)b * SEQ * CDIM + h * HD + c0;
        #pragma unroll
        for (int i = 0; i < 4; i++) {
            float4 r;
            r.x = acc[i][0]; r.y = acc[i][1]; r.z = acc[i][2]; r.w = acc[i][3];
            *(float4*)(obase + (size_t)(r0 + i) * CDIM) = r;
        }
    }
}

// ---------------------------------------------------------------------------
// Launch
// ---------------------------------------------------------------------------
extern "C" void kernel_launch(void* const* d_in, const int* in_sizes, int n_in,
                              void* d_out, int out_size) {
    const float* x          = (const float*)d_in[0]; // (256,128,768)
    const float* mask       = (const float*)d_in[1]; // (64,128,128)
    const float* qkv_w      = (const float*)d_in[2]; // (2304,768)
    const float* bias_table = (const float*)d_in[3]; // (255,12)
    const float* proj_w     = (const float*)d_in[4]; // (768,768)
    const float* proj_b     = (const float*)d_in[5]; // (768)
    float* out = (float*)d_out;

    float* qkv; cudaGetSymbolAddress((void**)&qkv, g_qkv);
    float* att; cudaGetSymbolAddress((void**)&att, g_att);

    cudaFuncSetAttribute(attn_kernel,
                         cudaFuncAttributeMaxDynamicSharedMemorySize,
                         ATTN_SMEM_BYTES);

    // 1) QKV projection: (32768,2304) = x @ qkv_w^T
    sgemm_abT<false><<<dim3(QKVDIM / 128, TOKENS / 128), 256>>>(
        x, qkv_w, nullptr, qkv, TOKENS, QKVDIM, CDIM);

    // 2) Fused attention per (b, h)
    attn_kernel<<<B_TOT * HEADS, 512, ATTN_SMEM_BYTES>>>(qkv, mask, bias_table, att);

    // 3) Output projection: out = att @ proj_w^T + proj_b
    sgemm_abT<true><<<dim3(CDIM / 128, TOKENS / 128), 256>>>(
        att, proj_w, proj_b, out, TOKENS, CDIM, CDIM);
}

// round 6
// speedup vs baseline: 2.4154x; 2.4154x over previous
#include <cuda_runtime.h>
#include <cstdint>
#include <cstddef>

// Problem constants
#define B_TOT   256
#define SEQ     128
#define CDIM    768
#define HEADS   12
#define HD      64
#define NWN     64
#define TOKENS  (B_TOT * SEQ)          // 32768
#define QKVDIM  (3 * CDIM)             // 2304

// Scratch (allocation-free rule: __device__ globals)
__device__ float g_qkv[(size_t)TOKENS * QKVDIM];
__device__ float g_att[(size_t)TOKENS * CDIM];

// ---------------------------------------------------------------------------
// Helpers
// ---------------------------------------------------------------------------
__device__ __forceinline__ uint32_t f2tf32(float x) {
    uint32_t r;
    asm("cvt.rna.tf32.f32 %0, %1;" : "=r"(r) : "f"(x));
    return r;
}

__device__ __forceinline__ void mma_tf32(float* c, const uint32_t* a, const uint32_t* b) {
    asm volatile("mma.sync.aligned.m16n8k8.row.col.f32.tf32.tf32.f32 "
        "{%0,%1,%2,%3}, {%4,%5,%6,%7}, {%8,%9}, {%0,%1,%2,%3};"
        : "+f"(c[0]), "+f"(c[1]), "+f"(c[2]), "+f"(c[3])
        : "r"(a[0]), "r"(a[1]), "r"(a[2]), "r"(a[3]), "r"(b[0]), "r"(b[1]));
}

// ---------------------------------------------------------------------------
// tf32 mma.sync GEMM: C[M,Nt] = A[M,K] @ W[Nt,K]^T (+bias)
// CTA tile 128x128, 8 warps (2m x 4n), warp tile 64x32 = 4x4 m16n8k8 tiles.
// K-chunk 16, double-buffered smem, pitch 20 words (conflict-free fragments).
// ---------------------------------------------------------------------------
#define PITCH 20

template<bool BIAS>
__global__ __launch_bounds__(256, 2)
void gemm_mma(const float* __restrict__ A, const float* __restrict__ W,
              const float* __restrict__ bias, float* __restrict__ C,
              int K, int ldc) {
    __shared__ uint32_t sA[2][128 * PITCH];
    __shared__ uint32_t sB[2][128 * PITCH];

    const int tid = threadIdx.x;
    const int bm = blockIdx.y * 128;
    const int bn = blockIdx.x * 128;
    const int nchunk = K / 16;

    // g2s coordinates: 4 threads per 16-float row, rows lrow and lrow+64
    const int quad = tid & 3;
    const int lrow = tid >> 2;               // 0..63
    const float* Aptr = A + (size_t)(bm + lrow) * K + quad * 4;
    const float* Wptr = W + (size_t)(bn + lrow) * K + quad * 4;
    const size_t rstep = (size_t)64 * K;

    // mma coordinates
    const int lane = tid & 31;
    const int g = lane >> 2;                 // groupID 0..7
    const int t = lane & 3;                  // thread in group
    const int wid = tid >> 5;
    const int wm = (wid & 1) * 64;           // warp m origin in tile
    const int wn = (wid >> 1) * 32;          // warp n origin in tile

    float4 ra0, ra1, rb0, rb1;
    auto ldg = [&](int c) {
        const float* a = Aptr + c * 16;
        const float* w = Wptr + c * 16;
        ra0 = *(const float4*)a;
        ra1 = *(const float4*)(a + rstep);
        rb0 = *(const float4*)w;
        rb1 = *(const float4*)(w + rstep);
    };
    auto sts = [&](int s) {
        const int base = lrow * PITCH + quad * 4;
        uint32_t* pa = &sA[s][base];
        pa[0] = f2tf32(ra0.x); pa[1] = f2tf32(ra0.y);
        pa[2] = f2tf32(ra0.z); pa[3] = f2tf32(ra0.w);
        uint32_t* pa2 = pa + 64 * PITCH;
        pa2[0] = f2tf32(ra1.x); pa2[1] = f2tf32(ra1.y);
        pa2[2] = f2tf32(ra1.z); pa2[3] = f2tf32(ra1.w);
        uint32_t* pb = &sB[s][base];
        pb[0] = f2tf32(rb0.x); pb[1] = f2tf32(rb0.y);
        pb[2] = f2tf32(rb0.z); pb[3] = f2tf32(rb0.w);
        uint32_t* pb2 = pb + 64 * PITCH;
        pb2[0] = f2tf32(rb1.x); pb2[1] = f2tf32(rb1.y);
        pb2[2] = f2tf32(rb1.z); pb2[3] = f2tf32(rb1.w);
    };

    float acc[4][4][4] = {};

    auto compute = [&](int s) {
        #pragma unroll
        for (int ks = 0; ks < 16; ks += 8) {
            uint32_t af[4][4], bf[4][2];
            #pragma unroll
            for (int i = 0; i < 4; i++) {
                const int ab = (wm + i * 16 + g) * PITCH + ks + t;
                af[i][0] = sA[s][ab];
                af[i][1] = sA[s][ab + 8 * PITCH];
                af[i][2] = sA[s][ab + 4];
                af[i][3] = sA[s][ab + 8 * PITCH + 4];
            }
            #pragma unroll
            for (int j = 0; j < 4; j++) {
                const int bb = (wn + j * 8 + g) * PITCH + ks + t;
                bf[j][0] = sB[s][bb];
                bf[j][1] = sB[s][bb + 4];
            }
            #pragma unroll
            for (int i = 0; i < 4; i++)
                #pragma unroll
                for (int j = 0; j < 4; j++)
                    mma_tf32(acc[i][j], af[i], bf[j]);
        }
    };

    ldg(0); sts(0); __syncthreads();
    #pragma unroll 1
    for (int c = 0; c < nchunk; ++c) {
        if (c + 1 < nchunk) ldg(c + 1);
        compute(c & 1);
        if (c + 1 < nchunk) sts((c + 1) & 1);
        __syncthreads();
    }

    // Epilogue: c0,c1 -> (row g, cols 2t,2t+1); c2,c3 -> row g+8
    #pragma unroll
    for (int i = 0; i < 4; i++) {
        const int r0 = bm + wm + i * 16 + g;
        #pragma unroll
        for (int j = 0; j < 4; j++) {
            const int cl = bn + wn + j * 8 + t * 2;
            float b0 = 0.f, b1 = 0.f;
            if (BIAS) { b0 = __ldg(bias + cl); b1 = __ldg(bias + cl + 1); }
            float2 v;
            v.x = acc[i][j][0] + b0; v.y = acc[i][j][1] + b1;
            *(float2*)(C + (size_t)r0 * ldc + cl) = v;
            v.x = acc[i][j][2] + b0; v.y = acc[i][j][3] + b1;
            *(float2*)(C + (size_t)(r0 + 8) * ldc + cl) = v;
        }
    }
}

// ---------------------------------------------------------------------------
// Fused window attention (unchanged — proven, rel_err 3.5e-7 path)
// ---------------------------------------------------------------------------
#define ATTN_SMEM_FLOATS 50560
#define ATTN_SMEM_BYTES  (ATTN_SMEM_FLOATS * 4)

__global__ __launch_bounds__(512)
void attn_kernel(const float* __restrict__ qkv, const float* __restrict__ mask,
                 const float* __restrict__ bias_table, float* __restrict__ att) {
    extern __shared__ float sm[];
    float* sq    = sm;            // [128][64]
    float* sktmp = sm + 8192;     // [128][65]
    float* skT   = sm + 16512;    // [64][128]
    float* sv    = sm + 24704;    // [128][68]
    float* sS    = sm + 33408;    // [128][132]
    float* sbias = sm + 50304;    // [255]

    const int tid = threadIdx.x;
    const int b = blockIdx.x / HEADS;
    const int h = blockIdx.x % HEADS;
    const int w = b & (NWN - 1);

    const float* base = qkv + (size_t)b * SEQ * QKVDIM + h * HD;

    for (int idx = tid; idx < SEQ * HD; idx += 512) {
        int n = idx >> 6, d = idx & 63;
        const float* p = base + (size_t)n * QKVDIM + d;
        sq[n * 64 + d]    = p[0] * 0.125f;
        sktmp[n * 65 + d] = p[CDIM];
        sv[n * 68 + d]    = p[2 * CDIM];
    }
    if (tid < 2 * SEQ - 1) sbias[tid] = bias_table[tid * HEADS + h];
    __syncthreads();

    for (int idx = tid; idx < SEQ * HD; idx += 512) {
        int n = idx & 127, d = idx >> 7;
        skT[d * 128 + n] = sktmp[n * 65 + d];
    }
    __syncthreads();

    {
        const int trow = tid >> 5;
        const int tcol = tid & 31;
        const int i0 = trow * 8, j0 = tcol * 4;
        float acc[8][4] = {};
        #pragma unroll 8
        for (int d = 0; d < 64; d++) {
            float4 b4 = *(const float4*)(skT + d * 128 + j0);
            #pragma unroll
            for (int i = 0; i < 8; i++) {
                float a = sq[(i0 + i) * 64 + d];
                acc[i][0] += a * b4.x; acc[i][1] += a * b4.y;
                acc[i][2] += a * b4.z; acc[i][3] += a * b4.w;
            }
        }
        const float4* m4 = (const float4*)(mask + (size_t)w * SEQ * SEQ);
        #pragma unroll
        for (int i = 0; i < 8; i++) {
            int ii = i0 + i;
            float4 mm = m4[(ii * SEQ + j0) >> 2];
            float4 r;
            r.x = acc[i][0] + sbias[ii - (j0 + 0) + SEQ - 1] + mm.x;
            r.y = acc[i][1] + sbias[ii - (j0 + 1) + SEQ - 1] + mm.y;
            r.z = acc[i][2] + sbias[ii - (j0 + 2) + SEQ - 1] + mm.z;
            r.w = acc[i][3] + sbias[ii - (j0 + 3) + SEQ - 1] + mm.w;
            *(float4*)(sS + ii * 132 + j0) = r;
        }
    }
    __syncthreads();

    {
        const int wid = tid >> 5, lane = tid & 31;
        for (int r = wid; r < SEQ; r += 16) {
            float* row = sS + r * 132;
            float v0 = row[lane], v1 = row[lane + 32];
            float v2 = row[lane + 64], v3 = row[lane + 96];
            float mx = fmaxf(fmaxf(v0, v1), fmaxf(v2, v3));
            #pragma unroll
            for (int o = 16; o; o >>= 1) mx = fmaxf(mx, __shfl_xor_sync(0xffffffffu, mx, o));
            v0 = __expf(v0 - mx); v1 = __expf(v1 - mx);
            v2 = __expf(v2 - mx); v3 = __expf(v3 - mx);
            float s = v0 + v1 + v2 + v3;
            #pragma unroll
            for (int o = 16; o; o >>= 1) s += __shfl_xor_sync(0xffffffffu, s, o);
            float inv = 1.0f / s;
            row[lane] = v0 * inv; row[lane + 32] = v1 * inv;
            row[lane + 64] = v2 * inv; row[lane + 96] = v3 * inv;
        }
    }
    __syncthreads();

    {
        const int trow = tid >> 4;
        const int tcol = tid & 15;
        const int r0 = trow * 4, c0 = tcol * 4;
        float acc[4][4] = {};
        #pragma unroll 8
        for (int m = 0; m < SEQ; m++) {
            float4 b4 = *(const float4*)(sv + m * 68 + c0);
            #pragma unroll
            for (int i = 0; i < 4; i++) {
                float a = sS[(r0 + i) * 132 + m];
                acc[i][0] += a * b4.x; acc[i][1] += a * b4.y;
                acc[i][2] += a * b4.z; acc[i][3] += a * b4.w;
            }
        }
        float* obase = att + (size_t)b * SEQ * CDIM + h * HD + c0;
        #pragma unroll
        for (int i = 0; i < 4; i++) {
            float4 r;
            r.x = acc[i][0]; r.y = acc[i][1]; r.z = acc[i][2]; r.w = acc[i][3];
            *(float4*)(obase + (size_t)(r0 + i) * CDIM) = r;
        }
    }
}

// ---------------------------------------------------------------------------
// Launch
// ---------------------------------------------------------------------------
extern "C" void kernel_launch(void* const* d_in, const int* in_sizes, int n_in,
                              void* d_out, int out_size) {
    const float* x          = (const float*)d_in[0];
    const float* mask       = (const float*)d_in[1];
    const float* qkv_w      = (const float*)d_in[2];
    const float* bias_table = (const float*)d_in[3];
    const float* proj_w     = (const float*)d_in[4];
    const float* proj_b     = (const float*)d_in[5];
    float* out = (float*)d_out;

    float* qkv; cudaGetSymbolAddress((void**)&qkv, g_qkv);
    float* att; cudaGetSymbolAddress((void**)&att, g_att);

    cudaFuncSetAttribute(attn_kernel,
                         cudaFuncAttributeMaxDynamicSharedMemorySize, ATTN_SMEM_BYTES);

    // 1) QKV projection: (32768,2304) = x @ qkv_w^T  (tf32 mma.sync)
    gemm_mma<false><<<dim3(QKVDIM / 128, TOKENS / 128), 256>>>(
        x, qkv_w, nullptr, qkv, CDIM, QKVDIM);

    // 2) Fused attention per (b, h)
    attn_kernel<<<B_TOT * HEADS, 512, ATTN_SMEM_BYTES>>>(qkv, mask, bias_table, att);

    // 3) Output projection: out = att @ proj_w^T + proj_b  (tf32 mma.sync)
    gemm_mma<true><<<dim3(CDIM / 128, TOKENS / 128), 256>>>(
        att, proj_w, proj_b, out, CDIM, CDIM);
}

// round 7
// speedup vs baseline: 2.5727x; 1.0651x over previous
#include <cuda_runtime.h>
#include <cstdint>
#include <cstddef>

// Problem constants
#define B_TOT   256
#define SEQ     128
#define CDIM    768
#define HEADS   12
#define HD      64
#define NWN     64
#define TOKENS  (B_TOT * SEQ)          // 32768
#define QKVDIM  (3 * CDIM)             // 2304

// Scratch (allocation-free rule: __device__ globals)
__device__ float g_qkv[(size_t)TOKENS * QKVDIM];
__device__ float g_att[(size_t)TOKENS * CDIM];

// ---------------------------------------------------------------------------
// Helpers
// ---------------------------------------------------------------------------
__device__ __forceinline__ uint32_t f2tf32(float x) {
    uint32_t r;
    asm("cvt.rna.tf32.f32 %0, %1;" : "=r"(r) : "f"(x));
    return r;
}

__device__ __forceinline__ void mma_tf32(float* c, const uint32_t* a, const uint32_t* b) {
    asm volatile("mma.sync.aligned.m16n8k8.row.col.f32.tf32.tf32.f32 "
        "{%0,%1,%2,%3}, {%4,%5,%6,%7}, {%8,%9}, {%0,%1,%2,%3};"
        : "+f"(c[0]), "+f"(c[1]), "+f"(c[2]), "+f"(c[3])
        : "r"(a[0]), "r"(a[1]), "r"(a[2]), "r"(a[3]), "r"(b[0]), "r"(b[1]));
}

// ---------------------------------------------------------------------------
// tf32 mma.sync GEMM: C[M,Nt] = A[M,K] @ W[Nt,K]^T (+bias)  (proven R6 kernel)
// ---------------------------------------------------------------------------
#define PITCH 20

template<bool BIAS>
__global__ __launch_bounds__(256, 2)
void gemm_mma(const float* __restrict__ A, const float* __restrict__ W,
              const float* __restrict__ bias, float* __restrict__ C,
              int K, int ldc) {
    __shared__ uint32_t sA[2][128 * PITCH];
    __shared__ uint32_t sB[2][128 * PITCH];

    const int tid = threadIdx.x;
    const int bm = blockIdx.y * 128;
    const int bn = blockIdx.x * 128;
    const int nchunk = K / 16;

    const int quad = tid & 3;
    const int lrow = tid >> 2;               // 0..63
    const float* Aptr = A + (size_t)(bm + lrow) * K + quad * 4;
    const float* Wptr = W + (size_t)(bn + lrow) * K + quad * 4;
    const size_t rstep = (size_t)64 * K;

    const int lane = tid & 31;
    const int g = lane >> 2;
    const int t = lane & 3;
    const int wid = tid >> 5;
    const int wm = (wid & 1) * 64;
    const int wn = (wid >> 1) * 32;

    float4 ra0, ra1, rb0, rb1;
    auto ldg = [&](int c) {
        const float* a = Aptr + c * 16;
        const float* w = Wptr + c * 16;
        ra0 = *(const float4*)a;
        ra1 = *(const float4*)(a + rstep);
        rb0 = *(const float4*)w;
        rb1 = *(const float4*)(w + rstep);
    };
    auto sts = [&](int s) {
        const int base = lrow * PITCH + quad * 4;
        uint32_t* pa = &sA[s][base];
        pa[0] = f2tf32(ra0.x); pa[1] = f2tf32(ra0.y);
        pa[2] = f2tf32(ra0.z); pa[3] = f2tf32(ra0.w);
        uint32_t* pa2 = pa + 64 * PITCH;
        pa2[0] = f2tf32(ra1.x); pa2[1] = f2tf32(ra1.y);
        pa2[2] = f2tf32(ra1.z); pa2[3] = f2tf32(ra1.w);
        uint32_t* pb = &sB[s][base];
        pb[0] = f2tf32(rb0.x); pb[1] = f2tf32(rb0.y);
        pb[2] = f2tf32(rb0.z); pb[3] = f2tf32(rb0.w);
        uint32_t* pb2 = pb + 64 * PITCH;
        pb2[0] = f2tf32(rb1.x); pb2[1] = f2tf32(rb1.y);
        pb2[2] = f2tf32(rb1.z); pb2[3] = f2tf32(rb1.w);
    };

    float acc[4][4][4] = {};

    auto compute = [&](int s) {
        #pragma unroll
        for (int ks = 0; ks < 16; ks += 8) {
            uint32_t af[4][4], bf[4][2];
            #pragma unroll
            for (int i = 0; i < 4; i++) {
                const int ab = (wm + i * 16 + g) * PITCH + ks + t;
                af[i][0] = sA[s][ab];
                af[i][1] = sA[s][ab + 8 * PITCH];
                af[i][2] = sA[s][ab + 4];
                af[i][3] = sA[s][ab + 8 * PITCH + 4];
            }
            #pragma unroll
            for (int j = 0; j < 4; j++) {
                const int bb = (wn + j * 8 + g) * PITCH + ks + t;
                bf[j][0] = sB[s][bb];
                bf[j][1] = sB[s][bb + 4];
            }
            #pragma unroll
            for (int i = 0; i < 4; i++)
                #pragma unroll
                for (int j = 0; j < 4; j++)
                    mma_tf32(acc[i][j], af[i], bf[j]);
        }
    };

    ldg(0); sts(0); __syncthreads();
    #pragma unroll 1
    for (int c = 0; c < nchunk; ++c) {
        if (c + 1 < nchunk) ldg(c + 1);
        compute(c & 1);
        if (c + 1 < nchunk) sts((c + 1) & 1);
        __syncthreads();
    }

    #pragma unroll
    for (int i = 0; i < 4; i++) {
        const int r0 = bm + wm + i * 16 + g;
        #pragma unroll
        for (int j = 0; j < 4; j++) {
            const int cl = bn + wn + j * 8 + t * 2;
            float b0 = 0.f, b1 = 0.f;
            if (BIAS) { b0 = __ldg(bias + cl); b1 = __ldg(bias + cl + 1); }
            float2 v;
            v.x = acc[i][j][0] + b0; v.y = acc[i][j][1] + b1;
            *(float2*)(C + (size_t)r0 * ldc + cl) = v;
            v.x = acc[i][j][2] + b0; v.y = acc[i][j][3] + b1;
            *(float2*)(C + (size_t)(r0 + 8) * ldc + cl) = v;
        }
    }
}

// ---------------------------------------------------------------------------
// Fused window attention v2: mma.sync tf32 for S = QK^T and P@V.
// One CTA per (b,h), 256 threads / 8 warps.
// smem (uint32 words): sq[128*68] sk[128*68] sv[128*68] sS[128*132] sbias[255]
// pitch 68 and 132 are ≡4 (mod 32) -> fragment LDS banks 4g+t, conflict-free.
// ---------------------------------------------------------------------------
#define AQ_PITCH 68
#define AS_PITCH 132
#define ATTN_SMEM_WORDS (3 * 128 * AQ_PITCH + 128 * AS_PITCH + 256)
#define ATTN_SMEM_BYTES (ATTN_SMEM_WORDS * 4)

__global__ __launch_bounds__(256)
void attn_kernel(const float* __restrict__ qkv, const float* __restrict__ mask,
                 const float* __restrict__ bias_table, float* __restrict__ att) {
    extern __shared__ uint32_t smu[];
    uint32_t* sq   = smu;                       // [128][68] tf32
    uint32_t* sk   = smu + 128 * AQ_PITCH;      // [128][68] tf32
    uint32_t* sv   = smu + 2 * 128 * AQ_PITCH;  // [128][68] tf32
    uint32_t* sSu  = smu + 3 * 128 * AQ_PITCH;  // [128][132]
    float*    sSf  = (float*)sSu;
    float*    sbias = (float*)(sSu + 128 * AS_PITCH);  // [255]

    const int tid = threadIdx.x;
    const int lane = tid & 31;
    const int g = lane >> 2;
    const int t = lane & 3;
    const int wid = tid >> 5;

    const int b = blockIdx.x / HEADS;
    const int h = blockIdx.x % HEADS;
    const int w = b & (NWN - 1);

    const float* base = qkv + (size_t)b * SEQ * QKVDIM + h * HD;
    const float* mrow = mask + (size_t)w * (SEQ * SEQ);

    // ---- Load q (scaled) / k / v with tf32 convert; preload mask into sS ----
    for (int it = tid; it < SEQ * (HD / 4); it += 256) {   // 2048 float4s
        const int r = it >> 4, c = (it & 15) * 4;
        const float* p = base + (size_t)r * QKVDIM + c;
        float4 q4 = *(const float4*)p;
        float4 k4 = *(const float4*)(p + CDIM);
        float4 v4 = *(const float4*)(p + 2 * CDIM);
        uint32_t* dq = sq + r * AQ_PITCH + c;
        dq[0] = f2tf32(q4.x * 0.125f); dq[1] = f2tf32(q4.y * 0.125f);
        dq[2] = f2tf32(q4.z * 0.125f); dq[3] = f2tf32(q4.w * 0.125f);
        uint32_t* dk = sk + r * AQ_PITCH + c;
        dk[0] = f2tf32(k4.x); dk[1] = f2tf32(k4.y);
        dk[2] = f2tf32(k4.z); dk[3] = f2tf32(k4.w);
        uint32_t* dv = sv + r * AQ_PITCH + c;
        dv[0] = f2tf32(v4.x); dv[1] = f2tf32(v4.y);
        dv[2] = f2tf32(v4.z); dv[3] = f2tf32(v4.w);
    }
    for (int it = tid; it < SEQ * SEQ / 4; it += 256) {    // 4096 float4s
        const int r = it >> 5, c = (it & 31) * 4;
        *(float4*)(sSf + r * AS_PITCH + c) = *(const float4*)(mrow + r * SEQ + c);
    }
    if (tid < 2 * SEQ - 1) sbias[tid] = bias_table[tid * HEADS + h];
    __syncthreads();

    // ---- S = q @ k^T  (warp tile 32m x 64n; 4m x 2n warp grid) ----
    {
        const int wm = (wid & 3) * 32;
        const int wn = (wid >> 2) * 64;
        float acc[2][8][4] = {};
        #pragma unroll
        for (int ks = 0; ks < HD; ks += 8) {
            uint32_t af[2][4], bf[8][2];
            #pragma unroll
            for (int i = 0; i < 2; i++) {
                const int ab = (wm + i * 16 + g) * AQ_PITCH + ks + t;
                af[i][0] = sq[ab];
                af[i][1] = sq[ab + 8 * AQ_PITCH];
                af[i][2] = sq[ab + 4];
                af[i][3] = sq[ab + 8 * AQ_PITCH + 4];
            }
            #pragma unroll
            for (int j = 0; j < 8; j++) {
                const int bb = (wn + j * 8 + g) * AQ_PITCH + ks + t;
                bf[j][0] = sk[bb];
                bf[j][1] = sk[bb + 4];
            }
            #pragma unroll
            for (int i = 0; i < 2; i++)
                #pragma unroll
                for (int j = 0; j < 8; j++)
                    mma_tf32(acc[i][j], af[i], bf[j]);
        }
        // Epilogue: S += mask(preloaded in sS) + rel-bias; write back to sS.
        // Owner-only read-modify-write: no extra sync needed before this.
        #pragma unroll
        for (int i = 0; i < 2; i++) {
            #pragma unroll
            for (int j = 0; j < 8; j++) {
                const int c = wn + j * 8 + t * 2;
                #pragma unroll
                for (int hh = 0; hh < 2; hh++) {
                    const int r = wm + i * 16 + g + hh * 8;
                    float* cell = sSf + r * AS_PITCH + c;
                    const float b0 = sbias[r - c + SEQ - 1];
                    const float b1 = sbias[r - c + SEQ - 2];
                    const float m0 = cell[0], m1 = cell[1];
                    cell[0] = acc[i][j][hh * 2 + 0] + m0 + b0;
                    cell[1] = acc[i][j][hh * 2 + 1] + m1 + b1;
                }
            }
        }
    }
    __syncthreads();

    // ---- Row softmax (8 warps, 16 rows each); writes P as tf32 bits ----
    {
        for (int r = wid; r < SEQ; r += 8) {
            float* row = sSf + r * AS_PITCH;
            float v0 = row[lane], v1 = row[lane + 32];
            float v2 = row[lane + 64], v3 = row[lane + 96];
            float mx = fmaxf(fmaxf(v0, v1), fmaxf(v2, v3));
            #pragma unroll
            for (int o = 16; o; o >>= 1) mx = fmaxf(mx, __shfl_xor_sync(0xffffffffu, mx, o));
            v0 = __expf(v0 - mx); v1 = __expf(v1 - mx);
            v2 = __expf(v2 - mx); v3 = __expf(v3 - mx);
            float s = v0 + v1 + v2 + v3;
            #pragma unroll
            for (int o = 16; o; o >>= 1) s += __shfl_xor_sync(0xffffffffu, s, o);
            const float inv = 1.0f / s;
            uint32_t* rowu = (uint32_t*)row;
            rowu[lane]      = f2tf32(v0 * inv);
            rowu[lane + 32] = f2tf32(v1 * inv);
            rowu[lane + 64] = f2tf32(v2 * inv);
            rowu[lane + 96] = f2tf32(v3 * inv);
        }
    }
    __syncthreads();

    // ---- out = P @ V  (warp tile 32m x 32n; 4m x 2n warp grid) ----
    {
        const int wm = (wid & 3) * 32;
        const int wn = (wid >> 2) * 32;
        float acc[2][4][4] = {};
        #pragma unroll 4
        for (int ks = 0; ks < SEQ; ks += 8) {
            uint32_t af[2][4], bf[4][2];
            #pragma unroll
            for (int i = 0; i < 2; i++) {
                const int ab = (wm + i * 16 + g) * AS_PITCH + ks + t;
                af[i][0] = sSu[ab];
                af[i][1] = sSu[ab + 8 * AS_PITCH];
                af[i][2] = sSu[ab + 4];
                af[i][3] = sSu[ab + 8 * AS_PITCH + 4];
            }
            #pragma unroll
            for (int j = 0; j < 4; j++) {
                const int bb = (ks + t) * AQ_PITCH + wn + j * 8 + g;
                bf[j][0] = sv[bb];
                bf[j][1] = sv[bb + 4 * AQ_PITCH];
            }
            #pragma unroll
            for (int i = 0; i < 2; i++)
                #pragma unroll
                for (int j = 0; j < 4; j++)
                    mma_tf32(acc[i][j], af[i], bf[j]);
        }
        float* obase = att + (size_t)b * SEQ * CDIM + h * HD;
        #pragma unroll
        for (int i = 0; i < 2; i++) {
            #pragma unroll
            for (int j = 0; j < 4; j++) {
                const int c = wn + j * 8 + t * 2;
                #pragma unroll
                for (int hh = 0; hh < 2; hh++) {
                    const int r = wm + i * 16 + g + hh * 8;
                    float2 v;
                    v.x = acc[i][j][hh * 2 + 0];
                    v.y = acc[i][j][hh * 2 + 1];
                    *(float2*)(obase + (size_t)r * CDIM + c) = v;
                }
            }
        }
    }
}

// ---------------------------------------------------------------------------
// Launch
// ---------------------------------------------------------------------------
extern "C" void kernel_launch(void* const* d_in, const int* in_sizes, int n_in,
                              void* d_out, int out_size) {
    const float* x          = (const float*)d_in[0];
    const float* mask       = (const float*)d_in[1];
    const float* qkv_w      = (const float*)d_in[2];
    const float* bias_table = (const float*)d_in[3];
    const float* proj_w     = (const float*)d_in[4];
    const float* proj_b     = (const float*)d_in[5];
    float* out = (float*)d_out;

    float* qkv; cudaGetSymbolAddress((void**)&qkv, g_qkv);
    float* att; cudaGetSymbolAddress((void**)&att, g_att);

    cudaFuncSetAttribute(attn_kernel,
                         cudaFuncAttributeMaxDynamicSharedMemorySize, ATTN_SMEM_BYTES);

    // 1) QKV projection: (32768,2304) = x @ qkv_w^T  (tf32 mma.sync)
    gemm_mma<false><<<dim3(QKVDIM / 128, TOKENS / 128), 256>>>(
        x, qkv_w, nullptr, qkv, CDIM, QKVDIM);

    // 2) Fused attention per (b, h)  (tf32 mma.sync)
    attn_kernel<<<B_TOT * HEADS, 256, ATTN_SMEM_BYTES>>>(qkv, mask, bias_table, att);

    // 3) Output projection: out = att @ proj_w^T + proj_b  (tf32 mma.sync)
    gemm_mma<true><<<dim3(CDIM / 128, TOKENS / 128), 256>>>(
        att, proj_w, proj_b, out, CDIM, CDIM);
}

// round 8
// speedup vs baseline: 2.8230x; 1.0973x over previous
#include <cuda_runtime.h>
#include <cstdint>
#include <cstddef>

// Problem constants
#define B_TOT   256
#define SEQ     128
#define CDIM    768
#define HEADS   12
#define HD      64
#define NWN     64
#define TOKENS  (B_TOT * SEQ)          // 32768
#define QKVDIM  (3 * CDIM)             // 2304

// Scratch (allocation-free rule: __device__ globals)
__device__ float g_qkv[(size_t)TOKENS * QKVDIM];
__device__ float g_att[(size_t)TOKENS * CDIM];

// ---------------------------------------------------------------------------
// Helpers
// ---------------------------------------------------------------------------
__device__ __forceinline__ uint32_t f2tf32(float x) {
    uint32_t r;
    asm("cvt.rna.tf32.f32 %0, %1;" : "=r"(r) : "f"(x));
    return r;
}

__device__ __forceinline__ void mma_tf32(float* c, const uint32_t* a, const uint32_t* b) {
    asm volatile("mma.sync.aligned.m16n8k8.row.col.f32.tf32.tf32.f32 "
        "{%0,%1,%2,%3}, {%4,%5,%6,%7}, {%8,%9}, {%0,%1,%2,%3};"
        : "+f"(c[0]), "+f"(c[1]), "+f"(c[2]), "+f"(c[3])
        : "r"(a[0]), "r"(a[1]), "r"(a[2]), "r"(a[3]), "r"(b[0]), "r"(b[1]));
}

// ldmatrix x4 (b16 form; bit-moving, valid for tf32 words)
__device__ __forceinline__ void ldsm_x4(uint32_t* r, uint32_t addr) {
    asm volatile("ldmatrix.sync.aligned.m8n8.x4.shared.b16 {%0,%1,%2,%3}, [%4];"
        : "=r"(r[0]), "=r"(r[1]), "=r"(r[2]), "=r"(r[3]) : "r"(addr));
}

// Per-lane offset pieces for ldmatrix fragment addressing.
// A-type x4 (m16k8 tile): lanes 0-7 rows 0-7/klo, 8-15 rows 8-15/klo,
//                         16-23 rows 0-7/khi, 24-31 rows 8-15/khi.
// B-type x4 (two n8k8 tiles): lanes 0-7 n 0-7/klo, 8-15 n 0-7/khi,
//                             16-23 n 8-15/klo, 24-31 n 8-15/khi.
#define A_LROW(lane) (((lane) & 7) + (((lane) >> 3) & 1) * 8)
#define A_LK(lane)   (((lane) >> 4) * 4)
#define B_LN(lane)   (((lane) & 7) + ((lane) >> 4) * 8)
#define B_LK(lane)   ((((lane) >> 3) & 1) * 4)

// ---------------------------------------------------------------------------
// tf32 mma.sync GEMM: C[M,Nt] = A[M,K] @ W[Nt,K]^T (+bias)
// CTA 128x128, 8 warps (2m x 4n), warp tile 64x32. K-chunk 16, double-buffered.
// Fragment loads via ldmatrix (6 LDSM per warp per k8).
// ---------------------------------------------------------------------------
#define PITCH 20

template<bool BIAS>
__global__ __launch_bounds__(256, 2)
void gemm_mma(const float* __restrict__ A, const float* __restrict__ W,
              const float* __restrict__ bias, float* __restrict__ C,
              int K, int ldc) {
    __shared__ uint32_t sA[2][128 * PITCH];
    __shared__ uint32_t sB[2][128 * PITCH];

    const int tid = threadIdx.x;
    const int bm = blockIdx.y * 128;
    const int bn = blockIdx.x * 128;
    const int nchunk = K / 16;

    const int quad = tid & 3;
    const int lrow = tid >> 2;               // 0..63
    const float* Aptr = A + (size_t)(bm + lrow) * K + quad * 4;
    const float* Wptr = W + (size_t)(bn + lrow) * K + quad * 4;
    const size_t rstep = (size_t)64 * K;

    const int lane = tid & 31;
    const int g = lane >> 2;
    const int t = lane & 3;
    const int wid = tid >> 5;
    const int wm = (wid & 1) * 64;
    const int wn = (wid >> 1) * 32;

    // ldmatrix per-lane base addresses (bytes), per buffer
    uint32_t aBase[2], bBase[2];
    {
        const uint32_t ar = A_LROW(lane), ak = A_LK(lane);
        const uint32_t bn_ = B_LN(lane), bk = B_LK(lane);
        #pragma unroll
        for (int s = 0; s < 2; s++) {
            aBase[s] = (uint32_t)__cvta_generic_to_shared(&sA[s][0])
                     + ((wm + ar) * PITCH + ak) * 4u;
            bBase[s] = (uint32_t)__cvta_generic_to_shared(&sB[s][0])
                     + ((wn + bn_) * PITCH + bk) * 4u;
        }
    }

    float4 ra0, ra1, rb0, rb1;
    auto ldg = [&](int c) {
        const float* a = Aptr + c * 16;
        const float* w = Wptr + c * 16;
        ra0 = *(const float4*)a;
        ra1 = *(const float4*)(a + rstep);
        rb0 = *(const float4*)w;
        rb1 = *(const float4*)(w + rstep);
    };
    auto sts = [&](int s) {
        const int base = lrow * PITCH + quad * 4;
        uint32_t* pa = &sA[s][base];
        pa[0] = f2tf32(ra0.x); pa[1] = f2tf32(ra0.y);
        pa[2] = f2tf32(ra0.z); pa[3] = f2tf32(ra0.w);
        uint32_t* pa2 = pa + 64 * PITCH;
        pa2[0] = f2tf32(ra1.x); pa2[1] = f2tf32(ra1.y);
        pa2[2] = f2tf32(ra1.z); pa2[3] = f2tf32(ra1.w);
        uint32_t* pb = &sB[s][base];
        pb[0] = f2tf32(rb0.x); pb[1] = f2tf32(rb0.y);
        pb[2] = f2tf32(rb0.z); pb[3] = f2tf32(rb0.w);
        uint32_t* pb2 = pb + 64 * PITCH;
        pb2[0] = f2tf32(rb1.x); pb2[1] = f2tf32(rb1.y);
        pb2[2] = f2tf32(rb1.z); pb2[3] = f2tf32(rb1.w);
    };

    float acc[4][4][4] = {};

    auto compute = [&](int s) {
        #pragma unroll
        for (int ks = 0; ks < 16; ks += 8) {
            uint32_t af[4][4], bf[4][2];
            #pragma unroll
            for (int i = 0; i < 4; i++)
                ldsm_x4(af[i], aBase[s] + (uint32_t)((i * 16 * PITCH + ks) * 4));
            #pragma unroll
            for (int j = 0; j < 4; j += 2) {
                uint32_t b4[4];
                ldsm_x4(b4, bBase[s] + (uint32_t)((j * 8 * PITCH + ks) * 4));
                bf[j][0] = b4[0]; bf[j][1] = b4[1];
                bf[j + 1][0] = b4[2]; bf[j + 1][1] = b4[3];
            }
            #pragma unroll
            for (int i = 0; i < 4; i++)
                #pragma unroll
                for (int j = 0; j < 4; j++)
                    mma_tf32(acc[i][j], af[i], bf[j]);
        }
    };

    ldg(0); sts(0); __syncthreads();
    #pragma unroll 1
    for (int c = 0; c < nchunk; ++c) {
        if (c + 1 < nchunk) ldg(c + 1);
        compute(c & 1);
        if (c + 1 < nchunk) sts((c + 1) & 1);
        __syncthreads();
    }

    #pragma unroll
    for (int i = 0; i < 4; i++) {
        const int r0 = bm + wm + i * 16 + g;
        #pragma unroll
        for (int j = 0; j < 4; j++) {
            const int cl = bn + wn + j * 8 + t * 2;
            float b0 = 0.f, b1 = 0.f;
            if (BIAS) { b0 = __ldg(bias + cl); b1 = __ldg(bias + cl + 1); }
            float2 v;
            v.x = acc[i][j][0] + b0; v.y = acc[i][j][1] + b1;
            *(float2*)(C + (size_t)r0 * ldc + cl) = v;
            v.x = acc[i][j][2] + b0; v.y = acc[i][j][3] + b1;
            *(float2*)(C + (size_t)(r0 + 8) * ldc + cl) = v;
        }
    }
}

// ---------------------------------------------------------------------------
// Fused window attention: mma.sync tf32, fragments via ldmatrix.
// One CTA per (b,h), 256 threads / 8 warps.
// ---------------------------------------------------------------------------
#define AQ_PITCH 68
#define AS_PITCH 132
#define ATTN_SMEM_WORDS (3 * 128 * AQ_PITCH + 128 * AS_PITCH + 256)
#define ATTN_SMEM_BYTES (ATTN_SMEM_WORDS * 4)

__global__ __launch_bounds__(256)
void attn_kernel(const float* __restrict__ qkv, const float* __restrict__ mask,
                 const float* __restrict__ bias_table, float* __restrict__ att) {
    extern __shared__ uint32_t smu[];
    uint32_t* sq   = smu;                       // [128][68] tf32
    uint32_t* sk   = smu + 128 * AQ_PITCH;      // [128][68] tf32
    uint32_t* sv   = smu + 2 * 128 * AQ_PITCH;  // [128][68] tf32
    uint32_t* sSu  = smu + 3 * 128 * AQ_PITCH;  // [128][132]
    float*    sSf  = (float*)sSu;
    float*    sbias = (float*)(sSu + 128 * AS_PITCH);  // [255]

    const int tid = threadIdx.x;
    const int lane = tid & 31;
    const int g = lane >> 2;
    const int t = lane & 3;
    const int wid = tid >> 5;

    const int b = blockIdx.x / HEADS;
    const int h = blockIdx.x % HEADS;
    const int w = b & (NWN - 1);

    const float* base = qkv + (size_t)b * SEQ * QKVDIM + h * HD;
    const float* mrow = mask + (size_t)w * (SEQ * SEQ);

    const uint32_t a_lr = A_LROW(lane), a_lk = A_LK(lane);
    const uint32_t b_ln = B_LN(lane),  b_lk = B_LK(lane);
    const uint32_t sq_a = (uint32_t)__cvta_generic_to_shared(sq);
    const uint32_t sk_a = (uint32_t)__cvta_generic_to_shared(sk);
    const uint32_t sS_a = (uint32_t)__cvta_generic_to_shared(sSu);

    // ---- Load q (scaled) / k / v with tf32 convert; preload mask into sS ----
    for (int it = tid; it < SEQ * (HD / 4); it += 256) {   // 2048 float4s
        const int r = it >> 4, c = (it & 15) * 4;
        const float* p = base + (size_t)r * QKVDIM + c;
        float4 q4 = *(const float4*)p;
        float4 k4 = *(const float4*)(p + CDIM);
        float4 v4 = *(const float4*)(p + 2 * CDIM);
        uint32_t* dq = sq + r * AQ_PITCH + c;
        dq[0] = f2tf32(q4.x * 0.125f); dq[1] = f2tf32(q4.y * 0.125f);
        dq[2] = f2tf32(q4.z * 0.125f); dq[3] = f2tf32(q4.w * 0.125f);
        uint32_t* dk = sk + r * AQ_PITCH + c;
        dk[0] = f2tf32(k4.x); dk[1] = f2tf32(k4.y);
        dk[2] = f2tf32(k4.z); dk[3] = f2tf32(k4.w);
        uint32_t* dv = sv + r * AQ_PITCH + c;
        dv[0] = f2tf32(v4.x); dv[1] = f2tf32(v4.y);
        dv[2] = f2tf32(v4.z); dv[3] = f2tf32(v4.w);
    }
    for (int it = tid; it < SEQ * SEQ / 4; it += 256) {    // 4096 float4s
        const int r = it >> 5, c = (it & 31) * 4;
        *(float4*)(sSf + r * AS_PITCH + c) = *(const float4*)(mrow + r * SEQ + c);
    }
    if (tid < 2 * SEQ - 1) sbias[tid] = bias_table[tid * HEADS + h];
    __syncthreads();

    // ---- S = q @ k^T  (warp tile 32m x 64n; 4m x 2n warp grid) ----
    {
        const int wm = (wid & 3) * 32;
        const int wn = (wid >> 2) * 64;
        const uint32_t aB = sq_a + ((wm + a_lr) * AQ_PITCH + a_lk) * 4u;
        const uint32_t bB = sk_a + ((wn + b_ln) * AQ_PITCH + b_lk) * 4u;
        float acc[2][8][4] = {};
        #pragma unroll
        for (int ks = 0; ks < HD; ks += 8) {
            uint32_t af[2][4], bf[8][2];
            #pragma unroll
            for (int i = 0; i < 2; i++)
                ldsm_x4(af[i], aB + (uint32_t)((i * 16 * AQ_PITCH + ks) * 4));
            #pragma unroll
            for (int j = 0; j < 8; j += 2) {
                uint32_t b4[4];
                ldsm_x4(b4, bB + (uint32_t)((j * 8 * AQ_PITCH + ks) * 4));
                bf[j][0] = b4[0]; bf[j][1] = b4[1];
                bf[j + 1][0] = b4[2]; bf[j + 1][1] = b4[3];
            }
            #pragma unroll
            for (int i = 0; i < 2; i++)
                #pragma unroll
                for (int j = 0; j < 8; j++)
                    mma_tf32(acc[i][j], af[i], bf[j]);
        }
        // S += mask(preloaded) + rel-bias; owner-only RMW into sS
        #pragma unroll
        for (int i = 0; i < 2; i++) {
            #pragma unroll
            for (int j = 0; j < 8; j++) {
                const int c = wn + j * 8 + t * 2;
                #pragma unroll
                for (int hh = 0; hh < 2; hh++) {
                    const int r = wm + i * 16 + g + hh * 8;
                    float* cell = sSf + r * AS_PITCH + c;
                    const float b0 = sbias[r - c + SEQ - 1];
                    const float b1 = sbias[r - c + SEQ - 2];
                    const float m0 = cell[0], m1 = cell[1];
                    cell[0] = acc[i][j][hh * 2 + 0] + m0 + b0;
                    cell[1] = acc[i][j][hh * 2 + 1] + m1 + b1;
                }
            }
        }
    }
    __syncthreads();

    // ---- Row softmax (8 warps, 16 rows each); writes P as tf32 bits ----
    {
        for (int r = wid; r < SEQ; r += 8) {
            float* row = sSf + r * AS_PITCH;
            float v0 = row[lane], v1 = row[lane + 32];
            float v2 = row[lane + 64], v3 = row[lane + 96];
            float mx = fmaxf(fmaxf(v0, v1), fmaxf(v2, v3));
            #pragma unroll
            for (int o = 16; o; o >>= 1) mx = fmaxf(mx, __shfl_xor_sync(0xffffffffu, mx, o));
            v0 = __expf(v0 - mx); v1 = __expf(v1 - mx);
            v2 = __expf(v2 - mx); v3 = __expf(v3 - mx);
            float s = v0 + v1 + v2 + v3;
            #pragma unroll
            for (int o = 16; o; o >>= 1) s += __shfl_xor_sync(0xffffffffu, s, o);
            const float inv = 1.0f / s;
            uint32_t* rowu = (uint32_t*)row;
            rowu[lane]      = f2tf32(v0 * inv);
            rowu[lane + 32] = f2tf32(v1 * inv);
            rowu[lane + 64] = f2tf32(v2 * inv);
            rowu[lane + 96] = f2tf32(v3 * inv);
        }
    }
    __syncthreads();

    // ---- out = P @ V  (warp tile 32m x 32n; 4m x 2n warp grid) ----
    {
        const int wm = (wid & 3) * 32;
        const int wn = (wid >> 2) * 32;
        const uint32_t aB = sS_a + ((wm + a_lr) * AS_PITCH + a_lk) * 4u;
        float acc[2][4][4] = {};
        #pragma unroll 4
        for (int ks = 0; ks < SEQ; ks += 8) {
            uint32_t af[2][4], bf[4][2];
            #pragma unroll
            for (int i = 0; i < 2; i++)
                ldsm_x4(af[i], aB + (uint32_t)((i * 16 * AS_PITCH + ks) * 4));
            #pragma unroll
            for (int j = 0; j < 4; j++) {
                const int bb = (ks + t) * AQ_PITCH + wn + j * 8 + g;
                bf[j][0] = sv[bb];
                bf[j][1] = sv[bb + 4 * AQ_PITCH];
            }
            #pragma unroll
            for (int i = 0; i < 2; i++)
                #pragma unroll
                for (int j = 0; j < 4; j++)
                    mma_tf32(acc[i][j], af[i], bf[j]);
        }
        float* obase = att + (size_t)b * SEQ * CDIM + h * HD;
        #pragma unroll
        for (int i = 0; i < 2; i++) {
            #pragma unroll
            for (int j = 0; j < 4; j++) {
                const int c = wn + j * 8 + t * 2;
                #pragma unroll
                for (int hh = 0; hh < 2; hh++) {
                    const int r = wm + i * 16 + g + hh * 8;
                    float2 v;
                    v.x = acc[i][j][hh * 2 + 0];
                    v.y = acc[i][j][hh * 2 + 1];
                    *(float2*)(obase + (size_t)r * CDIM + c) = v;
                }
            }
        }
    }
}

// ---------------------------------------------------------------------------
// Launch
// ---------------------------------------------------------------------------
extern "C" void kernel_launch(void* const* d_in, const int* in_sizes, int n_in,
                              void* d_out, int out_size) {
    const float* x          = (const float*)d_in[0];
    const float* mask       = (const float*)d_in[1];
    const float* qkv_w      = (const float*)d_in[2];
    const float* bias_table = (const float*)d_in[3];
    const float* proj_w     = (const float*)d_in[4];
    const float* proj_b     = (const float*)d_in[5];
    float* out = (float*)d_out;

    float* qkv; cudaGetSymbolAddress((void**)&qkv, g_qkv);
    float* att; cudaGetSymbolAddress((void**)&att, g_att);

    cudaFuncSetAttribute(attn_kernel,
                         cudaFuncAttributeMaxDynamicSharedMemorySize, ATTN_SMEM_BYTES);

    // 1) QKV projection: (32768,2304) = x @ qkv_w^T  (tf32 mma.sync + ldmatrix)
    gemm_mma<false><<<dim3(QKVDIM / 128, TOKENS / 128), 256>>>(
        x, qkv_w, nullptr, qkv, CDIM, QKVDIM);

    // 2) Fused attention per (b, h)
    attn_kernel<<<B_TOT * HEADS, 256, ATTN_SMEM_BYTES>>>(qkv, mask, bias_table, att);

    // 3) Output projection: out = att @ proj_w^T + proj_b
    gemm_mma<true><<<dim3(CDIM / 128, TOKENS / 128), 256>>>(
        att, proj_w, proj_b, out, CDIM, CDIM);
}

// round 10
// speedup vs baseline: 3.0042x; 1.0642x over previous
#include <cuda_runtime.h>
#include <cuda_fp16.h>
#include <cstdint>
#include <cstddef>

// Problem constants
#define B_TOT   256
#define SEQ     128
#define CDIM    768
#define HEADS   12
#define HD      64
#define NWN     64
#define TOKENS  (B_TOT * SEQ)          // 32768
#define QKVDIM  (3 * CDIM)             // 2304

// Scratch (allocation-free rule: __device__ globals)
__device__ float g_qkv[(size_t)TOKENS * QKVDIM];
__device__ float g_att[(size_t)TOKENS * CDIM];

// ---------------------------------------------------------------------------
// Helpers
// ---------------------------------------------------------------------------
__device__ __forceinline__ uint32_t f2tf32(float x) {
    uint32_t r;
    asm("cvt.rna.tf32.f32 %0, %1;" : "=r"(r) : "f"(x));
    return r;
}
__device__ __forceinline__ uint32_t pack_h2(float lo, float hi) {
    __half2 h = __floats2half2_rn(lo, hi);
    return *reinterpret_cast<uint32_t*>(&h);
}

__device__ __forceinline__ void mma_tf32(float* c, const uint32_t* a, const uint32_t* b) {
    asm volatile("mma.sync.aligned.m16n8k8.row.col.f32.tf32.tf32.f32 "
        "{%0,%1,%2,%3}, {%4,%5,%6,%7}, {%8,%9}, {%0,%1,%2,%3};"
        : "+f"(c[0]), "+f"(c[1]), "+f"(c[2]), "+f"(c[3])
        : "r"(a[0]), "r"(a[1]), "r"(a[2]), "r"(a[3]), "r"(b[0]), "r"(b[1]));
}
__device__ __forceinline__ void mma_f16(float* c, const uint32_t* a, const uint32_t* b) {
    asm volatile("mma.sync.aligned.m16n8k16.row.col.f32.f16.f16.f32 "
        "{%0,%1,%2,%3}, {%4,%5,%6,%7}, {%8,%9}, {%0,%1,%2,%3};"
        : "+f"(c[0]), "+f"(c[1]), "+f"(c[2]), "+f"(c[3])
        : "r"(a[0]), "r"(a[1]), "r"(a[2]), "r"(a[3]), "r"(b[0]), "r"(b[1]));
}

__device__ __forceinline__ void ldsm_x4(uint32_t* r, uint32_t addr) {
    asm volatile("ldmatrix.sync.aligned.m8n8.x4.shared.b16 {%0,%1,%2,%3}, [%4];"
        : "=r"(r[0]), "=r"(r[1]), "=r"(r[2]), "=r"(r[3]) : "r"(addr));
}

// Per-lane offset pieces for ldmatrix fragment addressing.
#define A_LROW(lane) (((lane) & 7) + (((lane) >> 3) & 1) * 8)
#define A_LK(lane)   (((lane) >> 4) * 4)
#define B_LN(lane)   (((lane) & 7) + ((lane) >> 4) * 8)
#define B_LK(lane)   ((((lane) >> 3) & 1) * 4)

// ---------------------------------------------------------------------------
// fp16 mma.sync GEMM: C[M,Nt] = A[M,K] @ W[Nt,K]^T (+bias), fp32 accum.
// CTA 128x128, 8 warps (2m x 4n), warp tile 64x32. K-chunk 16 (one k16 mma
// step), double-buffered smem. Row = 8 half2 words + 4 pad (GPITCH 12):
// every 8-row ldmatrix phase tiles all 32 banks exactly.
// ---------------------------------------------------------------------------
#define GPITCH 12

template<bool BIAS>
__global__ __launch_bounds__(256, 2)
void gemm_h(const float* __restrict__ A, const float* __restrict__ W,
            const float* __restrict__ bias, float* __restrict__ C,
            int K, int ldc) {
    __shared__ uint32_t sA[2][128 * GPITCH];
    __shared__ uint32_t sB[2][128 * GPITCH];

    const int tid = threadIdx.x;
    const int bm = blockIdx.y * 128;
    const int bn = blockIdx.x * 128;
    const int nchunk = K / 16;

    // g2s: 2 threads per row; thread owns 8 consecutive floats (-> 4 half2)
    const int q = tid & 1;
    const int lrow = tid >> 1;               // 0..127
    const float* Aptr = A + (size_t)(bm + lrow) * K + 8 * q;
    const float* Wptr = W + (size_t)(bn + lrow) * K + 8 * q;

    const int lane = tid & 31;
    const int g = lane >> 2;
    const int t = lane & 3;
    const int wid = tid >> 5;
    const int wm = (wid & 1) * 64;
    const int wn = (wid >> 1) * 32;

    uint32_t aBase[2], bBase[2];
    {
        const uint32_t ar = A_LROW(lane), ak = A_LK(lane);
        const uint32_t bn_ = B_LN(lane), bk = B_LK(lane);
        #pragma unroll
        for (int s = 0; s < 2; s++) {
            aBase[s] = (uint32_t)__cvta_generic_to_shared(&sA[s][0])
                     + ((wm + ar) * GPITCH + ak) * 4u;
            bBase[s] = (uint32_t)__cvta_generic_to_shared(&sB[s][0])
                     + ((wn + bn_) * GPITCH + bk) * 4u;
        }
    }

    float4 ra0, ra1, rb0, rb1;
    auto ldg = [&](int c) {
        const float* a = Aptr + c * 16;
        const float* w = Wptr + c * 16;
        ra0 = *(const float4*)a;
        ra1 = *(const float4*)(a + 4);
        rb0 = *(const float4*)w;
        rb1 = *(const float4*)(w + 4);
    };
    auto sts = [&](int s) {
        const int woff = lrow * GPITCH + 4 * q;
        uint32_t* pa = &sA[s][woff];
        pa[0] = pack_h2(ra0.x, ra0.y); pa[1] = pack_h2(ra0.z, ra0.w);
        pa[2] = pack_h2(ra1.x, ra1.y); pa[3] = pack_h2(ra1.z, ra1.w);
        uint32_t* pb = &sB[s][woff];
        pb[0] = pack_h2(rb0.x, rb0.y); pb[1] = pack_h2(rb0.z, rb0.w);
        pb[2] = pack_h2(rb1.x, rb1.y); pb[3] = pack_h2(rb1.z, rb1.w);
    };

    float acc[4][4][4] = {};

    auto compute = [&](int s) {
        uint32_t af[4][4], bf[4][2];
        #pragma unroll
        for (int i = 0; i < 4; i++)
            ldsm_x4(af[i], aBase[s] + (uint32_t)(i * 16 * GPITCH * 4));
        #pragma unroll
        for (int j = 0; j < 4; j += 2) {
            uint32_t b4[4];
            ldsm_x4(b4, bBase[s] + (uint32_t)(j * 8 * GPITCH * 4));
            bf[j][0] = b4[0]; bf[j][1] = b4[1];
            bf[j + 1][0] = b4[2]; bf[j + 1][1] = b4[3];
        }
        #pragma unroll
        for (int i = 0; i < 4; i++)
            #pragma unroll
            for (int j = 0; j < 4; j++)
                mma_f16(acc[i][j], af[i], bf[j]);
    };

    ldg(0); sts(0); __syncthreads();
    #pragma unroll 1
    for (int c = 0; c < nchunk; ++c) {
        if (c + 1 < nchunk) ldg(c + 1);
        compute(c & 1);
        if (c + 1 < nchunk) sts((c + 1) & 1);
        __syncthreads();
    }

    #pragma unroll
    for (int i = 0; i < 4; i++) {
        const int r0 = bm + wm + i * 16 + g;
        #pragma unroll
        for (int j = 0; j < 4; j++) {
            const int cl = bn + wn + j * 8 + t * 2;
            float b0 = 0.f, b1 = 0.f;
            if (BIAS) { b0 = __ldg(bias + cl); b1 = __ldg(bias + cl + 1); }
            float2 v;
            v.x = acc[i][j][0] + b0; v.y = acc[i][j][1] + b1;
            *(float2*)(C + (size_t)r0 * ldc + cl) = v;
            v.x = acc[i][j][2] + b0; v.y = acc[i][j][3] + b1;
            *(float2*)(C + (size_t)(r0 + 8) * ldc + cl) = v;
        }
    }
}

// ---------------------------------------------------------------------------
// Fused window attention: mma.sync tf32, fragments via ldmatrix. (R8, proven)
// ---------------------------------------------------------------------------
#define AQ_PITCH 68
#define AS_PITCH 132
#define ATTN_SMEM_WORDS (3 * 128 * AQ_PITCH + 128 * AS_PITCH + 256)
#define ATTN_SMEM_BYTES (ATTN_SMEM_WORDS * 4)

__global__ __launch_bounds__(256)
void attn_kernel(const float* __restrict__ qkv, const float* __restrict__ mask,
                 const float* __restrict__ bias_table, float* __restrict__ att) {
    extern __shared__ uint32_t smu[];
    uint32_t* sq   = smu;                       // [128][68] tf32
    uint32_t* sk   = smu + 128 * AQ_PITCH;      // [128][68] tf32
    uint32_t* sv   = smu + 2 * 128 * AQ_PITCH;  // [128][68] tf32
    uint32_t* sSu  = smu + 3 * 128 * AQ_PITCH;  // [128][132]
    float*    sSf  = (float*)sSu;
    float*    sbias = (float*)(sSu + 128 * AS_PITCH);  // [255]

    const int tid = threadIdx.x;
    const int lane = tid & 31;
    const int g = lane >> 2;
    const int t = lane & 3;
    const int wid = tid >> 5;

    const int b = blockIdx.x / HEADS;
    const int h = blockIdx.x % HEADS;
    const int w = b & (NWN - 1);

    const float* base = qkv + (size_t)b * SEQ * QKVDIM + h * HD;
    const float* mrow = mask + (size_t)w * (SEQ * SEQ);

    const uint32_t a_lr = A_LROW(lane), a_lk = A_LK(lane);
    const uint32_t b_ln = B_LN(lane),  b_lk = B_LK(lane);
    const uint32_t sq_a = (uint32_t)__cvta_generic_to_shared(sq);
    const uint32_t sk_a = (uint32_t)__cvta_generic_to_shared(sk);
    const uint32_t sS_a = (uint32_t)__cvta_generic_to_shared(sSu);

    for (int it = tid; it < SEQ * (HD / 4); it += 256) {
        const int r = it >> 4, c = (it & 15) * 4;
        const float* p = base + (size_t)r * QKVDIM + c;
        float4 q4 = *(const float4*)p;
        float4 k4 = *(const float4*)(p + CDIM);
        float4 v4 = *(const float4*)(p + 2 * CDIM);
        uint32_t* dq = sq + r * AQ_PITCH + c;
        dq[0] = f2tf32(q4.x * 0.125f); dq[1] = f2tf32(q4.y * 0.125f);
        dq[2] = f2tf32(q4.z * 0.125f); dq[3] = f2tf32(q4.w * 0.125f);
        uint32_t* dk = sk + r * AQ_PITCH + c;
        dk[0] = f2tf32(k4.x); dk[1] = f2tf32(k4.y);
        dk[2] = f2tf32(k4.z); dk[3] = f2tf32(k4.w);
        uint32_t* dv = sv + r * AQ_PITCH + c;
        dv[0] = f2tf32(v4.x); dv[1] = f2tf32(v4.y);
        dv[2] = f2tf32(v4.z); dv[3] = f2tf32(v4.w);
    }
    for (int it = tid; it < SEQ * SEQ / 4; it += 256) {
        const int r = it >> 5, c = (it & 31) * 4;
        *(float4*)(sSf + r * AS_PITCH + c) = *(const float4*)(mrow + r * SEQ + c);
    }
    if (tid < 2 * SEQ - 1) sbias[tid] = bias_table[tid * HEADS + h];
    __syncthreads();

    // ---- S = q @ k^T ----
    {
        const int wm = (wid & 3) * 32;
        const int wn = (wid >> 2) * 64;
        const uint32_t aB = sq_a + ((wm + a_lr) * AQ_PITCH + a_lk) * 4u;
        const uint32_t bB = sk_a + ((wn + b_ln) * AQ_PITCH + b_lk) * 4u;
        float acc[2][8][4] = {};
        #pragma unroll
        for (int ks = 0; ks < HD; ks += 8) {
            uint32_t af[2][4], bf[8][2];
            #pragma unroll
            for (int i = 0; i < 2; i++)
                ldsm_x4(af[i], aB + (uint32_t)((i * 16 * AQ_PITCH + ks) * 4));
            #pragma unroll
            for (int j = 0; j < 8; j += 2) {
                uint32_t b4[4];
                ldsm_x4(b4, bB + (uint32_t)((j * 8 * AQ_PITCH + ks) * 4));
                bf[j][0] = b4[0]; bf[j][1] = b4[1];
                bf[j + 1][0] = b4[2]; bf[j + 1][1] = b4[3];
            }
            #pragma unroll
            for (int i = 0; i < 2; i++)
                #pragma unroll
                for (int j = 0; j < 8; j++)
                    mma_tf32(acc[i][j], af[i], bf[j]);
        }
        #pragma unroll
        for (int i = 0; i < 2; i++) {
            #pragma unroll
            for (int j = 0; j < 8; j++) {
                const int c = wn + j * 8 + t * 2;
                #pragma unroll
                for (int hh = 0; hh < 2; hh++) {
                    const int r = wm + i * 16 + g + hh * 8;
                    float* cell = sSf + r * AS_PITCH + c;
                    const float b0 = sbias[r - c + SEQ - 1];
                    const float b1 = sbias[r - c + SEQ - 2];
                    const float m0 = cell[0], m1 = cell[1];
                    cell[0] = acc[i][j][hh * 2 + 0] + m0 + b0;
                    cell[1] = acc[i][j][hh * 2 + 1] + m1 + b1;
                }
            }
        }
    }
    __syncthreads();

    // ---- Row softmax; writes P as tf32 bits ----
    {
        for (int r = wid; r < SEQ; r += 8) {
            float* row = sSf + r * AS_PITCH;
            float v0 = row[lane], v1 = row[lane + 32];
            float v2 = row[lane + 64], v3 = row[lane + 96];
            float mx = fmaxf(fmaxf(v0, v1), fmaxf(v2, v3));
            #pragma unroll
            for (int o = 16; o; o >>= 1) mx = fmaxf(mx, __shfl_xor_sync(0xffffffffu, mx, o));
            v0 = __expf(v0 - mx); v1 = __expf(v1 - mx);
            v2 = __expf(v2 - mx); v3 = __expf(v3 - mx);
            float s = v0 + v1 + v2 + v3;
            #pragma unroll
            for (int o = 16; o; o >>= 1) s += __shfl_xor_sync(0xffffffffu, s, o);
            const float inv = 1.0f / s;
            uint32_t* rowu = (uint32_t*)row;
            rowu[lane]      = f2tf32(v0 * inv);
            rowu[lane + 32] = f2tf32(v1 * inv);
            rowu[lane + 64] = f2tf32(v2 * inv);
            rowu[lane + 96] = f2tf32(v3 * inv);
        }
    }
    __syncthreads();

    // ---- out = P @ V ----
    {
        const int wm = (wid & 3) * 32;
        const int wn = (wid >> 2) * 32;
        const uint32_t aB = sS_a + ((wm + a_lr) * AS_PITCH + a_lk) * 4u;
        float acc[2][4][4] = {};
        #pragma unroll 4
        for (int ks = 0; ks < SEQ; ks += 8) {
            uint32_t af[2][4], bf[4][2];
            #pragma unroll
            for (int i = 0; i < 2; i++)
                ldsm_x4(af[i], aB + (uint32_t)((i * 16 * AS_PITCH + ks) * 4));
            #pragma unroll
            for (int j = 0; j < 4; j++) {
                const int bb = (ks + t) * AQ_PITCH + wn + j * 8 + g;
                bf[j][0] = sv[bb];
                bf[j][1] = sv[bb + 4 * AQ_PITCH];
            }
            #pragma unroll
            for (int i = 0; i < 2; i++)
                #pragma unroll
                for (int j = 0; j < 4; j++)
                    mma_tf32(acc[i][j], af[i], bf[j]);
        }
        float* obase = att + (size_t)b * SEQ * CDIM + h * HD;
        #pragma unroll
        for (int i = 0; i < 2; i++) {
            #pragma unroll
            for (int j = 0; j < 4; j++) {
                const int c = wn + j * 8 + t * 2;
                #pragma unroll
                for (int hh = 0; hh < 2; hh++) {
                    const int r = wm + i * 16 + g + hh * 8;
                    float2 v;
                    v.x = acc[i][j][hh * 2 + 0];
                    v.y = acc[i][j][hh * 2 + 1];
                    *(float2*)(obase + (size_t)r * CDIM + c) = v;
                }
            }
        }
    }
}

// ---------------------------------------------------------------------------
// Launch
// ---------------------------------------------------------------------------
extern "C" void kernel_launch(void* const* d_in, const int* in_sizes, int n_in,
                              void* d_out, int out_size) {
    const float* x          = (const float*)d_in[0];
    const float* mask       = (const float*)d_in[1];
    const float* qkv_w      = (const float*)d_in[2];
    const float* bias_table = (const float*)d_in[3];
    const float* proj_w     = (const float*)d_in[4];
    const float* proj_b     = (const float*)d_in[5];
    float* out = (float*)d_out;

    float* qkv; cudaGetSymbolAddress((void**)&qkv, g_qkv);
    float* att; cudaGetSymbolAddress((void**)&att, g_att);

    cudaFuncSetAttribute(attn_kernel,
                         cudaFuncAttributeMaxDynamicSharedMemorySize, ATTN_SMEM_BYTES);

    // 1) QKV projection: (32768,2304) = x @ qkv_w^T  (fp16 mma.sync)
    gemm_h<false><<<dim3(QKVDIM / 128, TOKENS / 128), 256>>>(
        x, qkv_w, nullptr, qkv, CDIM, QKVDIM);

    // 2) Fused attention per (b, h)  (tf32 mma.sync)
    attn_kernel<<<B_TOT * HEADS, 256, ATTN_SMEM_BYTES>>>(qkv, mask, bias_table, att);

    // 3) Output projection: out = att @ proj_w^T + proj_b  (fp16 mma.sync)
    gemm_h<true><<<dim3(CDIM / 128, TOKENS / 128), 256>>>(
        att, proj_w, proj_b, out, CDIM, CDIM);
}

// round 12
// speedup vs baseline: 4.1829x; 1.3923x over previous
#include <cuda_runtime.h>
#include <cuda_fp16.h>
#include <cstdint>
#include <cstddef>

// Problem constants
#define B_TOT   256
#define SEQ     128
#define CDIM    768
#define HEADS   12
#define HD      64
#define NWN     64
#define TOKENS  (B_TOT * SEQ)          // 32768
#define QKVDIM  (3 * CDIM)             // 2304

// Scratch (allocation-free rule: __device__ globals) — fp16 intermediates
__device__ __half g_qkv_h[(size_t)TOKENS * QKVDIM];
__device__ __half g_att_h[(size_t)TOKENS * CDIM];
__device__ __half g_wh[(size_t)(QKVDIM + CDIM) * CDIM];   // qkv_w then proj_w

// ---------------------------------------------------------------------------
// Helpers
// ---------------------------------------------------------------------------
__device__ __forceinline__ uint32_t f2tf32(float x) {
    uint32_t r;
    asm("cvt.rna.tf32.f32 %0, %1;" : "=r"(r) : "f"(x));
    return r;
}
__device__ __forceinline__ uint32_t pack_h2(float lo, float hi) {
    __half2 h = __floats2half2_rn(lo, hi);
    return *reinterpret_cast<uint32_t*>(&h);
}

__device__ __forceinline__ void mma_tf32(float* c, const uint32_t* a, const uint32_t* b) {
    asm volatile("mma.sync.aligned.m16n8k8.row.col.f32.tf32.tf32.f32 "
        "{%0,%1,%2,%3}, {%4,%5,%6,%7}, {%8,%9}, {%0,%1,%2,%3};"
        : "+f"(c[0]), "+f"(c[1]), "+f"(c[2]), "+f"(c[3])
        : "r"(a[0]), "r"(a[1]), "r"(a[2]), "r"(a[3]), "r"(b[0]), "r"(b[1]));
}
__device__ __forceinline__ void mma_f16(float* c, const uint32_t* a, const uint32_t* b) {
    asm volatile("mma.sync.aligned.m16n8k16.row.col.f32.f16.f16.f32 "
        "{%0,%1,%2,%3}, {%4,%5,%6,%7}, {%8,%9}, {%0,%1,%2,%3};"
        : "+f"(c[0]), "+f"(c[1]), "+f"(c[2]), "+f"(c[3])
        : "r"(a[0]), "r"(a[1]), "r"(a[2]), "r"(a[3]), "r"(b[0]), "r"(b[1]));
}
__device__ __forceinline__ void ldsm_x4(uint32_t* r, uint32_t addr) {
    asm volatile("ldmatrix.sync.aligned.m8n8.x4.shared.b16 {%0,%1,%2,%3}, [%4];"
        : "=r"(r[0]), "=r"(r[1]), "=r"(r[2]), "=r"(r[3]) : "r"(addr));
}
__device__ __forceinline__ void cp16(uint32_t dst, const void* src) {
    asm volatile("cp.async.cg.shared.global [%0], [%1], 16;"
                 :: "r"(dst), "l"(src));
}
__device__ __forceinline__ void cp_commit() {
    asm volatile("cp.async.commit_group;");
}

// Per-lane offset pieces for ldmatrix fragment addressing.
#define A_LROW(lane) (((lane) & 7) + (((lane) >> 3) & 1) * 8)
#define A_LK(lane)   (((lane) >> 4) * 4)
#define B_LN(lane)   (((lane) & 7) + ((lane) >> 4) * 8)
#define B_LK(lane)   ((((lane) >> 3) & 1) * 4)

// ---------------------------------------------------------------------------
// Weight pre-convert: fp32 -> fp16 (qkv_w then proj_w), vectorized
// ---------------------------------------------------------------------------
__global__ void cvt_weights(const float4* __restrict__ qw,
                            const float4* __restrict__ pw) {
    const int n1 = (QKVDIM * CDIM) / 4;              // 442368
    const int nt = n1 + (CDIM * CDIM) / 4;           // 589824
    const int i = blockIdx.x * blockDim.x + threadIdx.x;
    if (i >= nt) return;
    float4 v = (i < n1) ? qw[i] : pw[i - n1];
    uint2 o;
    o.x = pack_h2(v.x, v.y);
    o.y = pack_h2(v.z, v.w);
    reinterpret_cast<uint2*>(g_wh)[i] = o;
}

// ---------------------------------------------------------------------------
// fp16 mma.sync GEMM: C[M,Nt] = A[M,K] @ W[Nt,K]^T (+bias), fp32 accum.
// CTA 128x256, 8 warps (2m x 4n), warp tile 64x64. K-chunk 32 (two k16 mma
// steps). B (weights, fp16) via cp.async; A fp32 LDG+cvt or fp16 cp.async.
// Row layout: 16 h2 words + 4 pad (GP 20) — ldmatrix 8-row phases tile all
// 32 banks (20r mod 32 = {0,20,8,28,16,4,24,12}).
// ---------------------------------------------------------------------------
#define GP 20
#define GEMM_DSMEM ((2 * 128 + 2 * 256) * GP * 4)    // 61440 B

template<bool A_HALF, bool OUT_HALF>
__global__ __launch_bounds__(256)
void gemm_h2(const void* __restrict__ Av, const __half* __restrict__ W,
             const float* __restrict__ bias, void* __restrict__ Cv,
             int K, int ldc) {
    extern __shared__ uint32_t dsm[];
    uint32_t* sA = dsm;                       // [2][128*GP]
    uint32_t* sB = dsm + 2 * 128 * GP;        // [2][256*GP]

    const int tid = threadIdx.x;
    const int bm = blockIdx.y * 128;
    const int bn = blockIdx.x * 256;
    const int nchunk = K / 32;

    const uint32_t sA_u = (uint32_t)__cvta_generic_to_shared(sA);
    const uint32_t sB_u = (uint32_t)__cvta_generic_to_shared(sB);

    // cp.async coords: 4 lanes per 64B fp16 row
    const int rB  = tid >> 2;                 // 0..63
    const int sg  = tid & 3;                  // 16B segment
    // A fp32 coords: 8 lanes per 128B row
    const int rA  = tid >> 3;                 // 0..31
    const int cA  = (tid & 7) * 4;

    const float* Af = (const float*)Av;
    const __half* Ah = (const __half*)Av;

    const int lane = tid & 31;
    const int g = lane >> 2;
    const int t = lane & 3;
    const int wid = tid >> 5;
    const int wm = (wid & 1) * 64;
    const int wn = (wid >> 1) * 64;

    const uint32_t a_lr = A_LROW(lane), a_lk = A_LK(lane);
    const uint32_t b_ln = B_LN(lane),  b_lk = B_LK(lane);

    auto issue_cp = [&](int c) {
        const int s = c & 1;
        const int k0 = c * 32;
        #pragma unroll
        for (int p = 0; p < 4; p++) {
            const int r = rB + 64 * p;
            cp16(sB_u + (uint32_t)((((s * 256 + r) * GP) + sg * 4) * 4),
                 W + (size_t)(bn + r) * K + k0 + sg * 8);
        }
        if (A_HALF) {
            #pragma unroll
            for (int p = 0; p < 2; p++) {
                const int r = rB + 64 * p;
                cp16(sA_u + (uint32_t)((((s * 128 + r) * GP) + sg * 4) * 4),
                     Ah + (size_t)(bm + r) * K + k0 + sg * 8);
            }
        }
        cp_commit();
    };

    float4 fa[4];
    auto ldgA = [&](int c) {
        if (!A_HALF) {
            const int k0 = c * 32;
            #pragma unroll
            for (int p = 0; p < 4; p++)
                fa[p] = *(const float4*)(Af + (size_t)(bm + rA + 32 * p) * K + k0 + cA);
        }
    };
    auto stsA = [&](int s) {
        if (!A_HALF) {
            #pragma unroll
            for (int p = 0; p < 4; p++) {
                uint32_t* d = sA + (s * 128 + rA + 32 * p) * GP + (tid & 7) * 2;
                d[0] = pack_h2(fa[p].x, fa[p].y);
                d[1] = pack_h2(fa[p].z, fa[p].w);
            }
        }
    };

    float acc[4][8][4] = {};

    auto compute = [&](int s) {
        const uint32_t aB = sA_u + (uint32_t)((((s * 128 + wm + a_lr) * GP) + a_lk) * 4);
        const uint32_t bB = sB_u + (uint32_t)((((s * 256 + wn + b_ln) * GP) + b_lk) * 4);
        #pragma unroll
        for (int ks = 0; ks < 2; ks++) {
            uint32_t af[4][4], bf[8][2];
            #pragma unroll
            for (int i = 0; i < 4; i++)
                ldsm_x4(af[i], aB + (uint32_t)((i * 16 * GP + ks * 8) * 4));
            #pragma unroll
            for (int jj = 0; jj < 4; jj++) {
                uint32_t b4[4];
                ldsm_x4(b4, bB + (uint32_t)((jj * 16 * GP + ks * 8) * 4));
                bf[2 * jj][0] = b4[0]; bf[2 * jj][1] = b4[1];
                bf[2 * jj + 1][0] = b4[2]; bf[2 * jj + 1][1] = b4[3];
            }
            #pragma unroll
            for (int i = 0; i < 4; i++)
                #pragma unroll
                for (int j = 0; j < 8; j++)
                    mma_f16(acc[i][j], af[i], bf[j]);
        }
    };

    issue_cp(0);
    ldgA(0);
    #pragma unroll 1
    for (int c = 0; c < nchunk; ++c) {
        stsA(c & 1);
        if (c + 1 < nchunk) {
            issue_cp(c + 1);
            ldgA(c + 1);
            asm volatile("cp.async.wait_group 1;");
        } else {
            asm volatile("cp.async.wait_group 0;");
        }
        __syncthreads();
        compute(c & 1);
        if (c + 1 < nchunk) __syncthreads();
    }

    // Epilogue
    #pragma unroll
    for (int i = 0; i < 4; i++) {
        const int r0 = bm + wm + i * 16 + g;
        #pragma unroll
        for (int j = 0; j < 8; j++) {
            const int cl = bn + wn + j * 8 + t * 2;
            if (OUT_HALF) {
                __half* C = (__half*)Cv;
                *(uint32_t*)(C + (size_t)r0 * ldc + cl) =
                    pack_h2(acc[i][j][0], acc[i][j][1]);
                *(uint32_t*)(C + (size_t)(r0 + 8) * ldc + cl) =
                    pack_h2(acc[i][j][2], acc[i][j][3]);
            } else {
                float* C = (float*)Cv;
                float b0 = 0.f, b1 = 0.f;
                if (bias) { b0 = __ldg(bias + cl); b1 = __ldg(bias + cl + 1); }
                float2 v;
                v.x = acc[i][j][0] + b0; v.y = acc[i][j][1] + b1;
                *(float2*)(C + (size_t)r0 * ldc + cl) = v;
                v.x = acc[i][j][2] + b0; v.y = acc[i][j][3] + b1;
                *(float2*)(C + (size_t)(r0 + 8) * ldc + cl) = v;
            }
        }
    }
}

// ---------------------------------------------------------------------------
// Fused window attention: mma.sync tf32 core (proven R8), fp16 gmem I/O.
// ---------------------------------------------------------------------------
#define AQ_PITCH 68
#define AS_PITCH 132
#define ATTN_SMEM_WORDS (3 * 128 * AQ_PITCH + 128 * AS_PITCH + 256)
#define ATTN_SMEM_BYTES (ATTN_SMEM_WORDS * 4)

__global__ __launch_bounds__(256)
void attn_kernel(const __half* __restrict__ qkv, const float* __restrict__ mask,
                 const float* __restrict__ bias_table, __half* __restrict__ att) {
    extern __shared__ uint32_t smu[];
    uint32_t* sq   = smu;                       // [128][68] tf32
    uint32_t* sk   = smu + 128 * AQ_PITCH;      // [128][68] tf32
    uint32_t* sv   = smu + 2 * 128 * AQ_PITCH;  // [128][68] tf32
    uint32_t* sSu  = smu + 3 * 128 * AQ_PITCH;  // [128][132]
    float*    sSf  = (float*)sSu;
    float*    sbias = (float*)(sSu + 128 * AS_PITCH);  // [255]

    const int tid = threadIdx.x;
    const int lane = tid & 31;
    const int g = lane >> 2;
    const int t = lane & 3;
    const int wid = tid >> 5;

    const int b = blockIdx.x / HEADS;
    const int h = blockIdx.x % HEADS;
    const int w = b & (NWN - 1);

    const __half* base = qkv + (size_t)b * SEQ * QKVDIM + h * HD;
    const float* mrow = mask + (size_t)w * (SEQ * SEQ);

    const uint32_t a_lr = A_LROW(lane), a_lk = A_LK(lane);
    const uint32_t b_ln = B_LN(lane),  b_lk = B_LK(lane);
    const uint32_t sq_a = (uint32_t)__cvta_generic_to_shared(sq);
    const uint32_t sk_a = (uint32_t)__cvta_generic_to_shared(sk);
    const uint32_t sS_a = (uint32_t)__cvta_generic_to_shared(sSu);

    // ---- Load q/k/v (fp16 gmem -> tf32 smem; q pre-scaled) ----
    for (int it = tid; it < SEQ * (HD / 4); it += 256) {
        const int r = it >> 4, c = (it & 15) * 4;
        const __half2* p = (const __half2*)(base + (size_t)r * QKVDIM + c);
        float2 q0 = __half22float2(p[0]),            q1 = __half22float2(p[1]);
        float2 k0 = __half22float2(p[CDIM / 2]),     k1 = __half22float2(p[CDIM / 2 + 1]);
        float2 v0 = __half22float2(p[CDIM]),         v1 = __half22float2(p[CDIM + 1]);
        uint32_t* dq = sq + r * AQ_PITCH + c;
        dq[0] = f2tf32(q0.x * 0.125f); dq[1] = f2tf32(q0.y * 0.125f);
        dq[2] = f2tf32(q1.x * 0.125f); dq[3] = f2tf32(q1.y * 0.125f);
        uint32_t* dk = sk + r * AQ_PITCH + c;
        dk[0] = f2tf32(k0.x); dk[1] = f2tf32(k0.y);
        dk[2] = f2tf32(k1.x); dk[3] = f2tf32(k1.y);
        uint32_t* dv = sv + r * AQ_PITCH + c;
        dv[0] = f2tf32(v0.x); dv[1] = f2tf32(v0.y);
        dv[2] = f2tf32(v1.x); dv[3] = f2tf32(v1.y);
    }
    for (int it = tid; it < SEQ * SEQ / 4; it += 256) {
        const int r = it >> 5, c = (it & 31) * 4;
        *(float4*)(sSf + r * AS_PITCH + c) = *(const float4*)(mrow + r * SEQ + c);
    }
    if (tid < 2 * SEQ - 1) sbias[tid] = bias_table[tid * HEADS + h];
    __syncthreads();

    // ---- S = q @ k^T ----
    {
        const int wm = (wid & 3) * 32;
        const int wn = (wid >> 2) * 64;
        const uint32_t aB = sq_a + ((wm + a_lr) * AQ_PITCH + a_lk) * 4u;
        const uint32_t bB = sk_a + ((wn + b_ln) * AQ_PITCH + b_lk) * 4u;
        float acc[2][8][4] = {};
        #pragma unroll
        for (int ks = 0; ks < HD; ks += 8) {
            uint32_t af[2][4], bf[8][2];
            #pragma unroll
            for (int i = 0; i < 2; i++)
                ldsm_x4(af[i], aB + (uint32_t)((i * 16 * AQ_PITCH + ks) * 4));
            #pragma unroll
            for (int j = 0; j < 8; j += 2) {
                uint32_t b4[4];
                ldsm_x4(b4, bB + (uint32_t)((j * 8 * AQ_PITCH + ks) * 4));
                bf[j][0] = b4[0]; bf[j][1] = b4[1];
                bf[j + 1][0] = b4[2]; bf[j + 1][1] = b4[3];
            }
            #pragma unroll
            for (int i = 0; i < 2; i++)
                #pragma unroll
                for (int j = 0; j < 8; j++)
                    mma_tf32(acc[i][j], af[i], bf[j]);
        }
        #pragma unroll
        for (int i = 0; i < 2; i++) {
            #pragma unroll
            for (int j = 0; j < 8; j++) {
                const int c = wn + j * 8 + t * 2;
                #pragma unroll
                for (int hh = 0; hh < 2; hh++) {
                    const int r = wm + i * 16 + g + hh * 8;
                    float* cell = sSf + r * AS_PITCH + c;
                    const float b0 = sbias[r - c + SEQ - 1];
                    const float b1 = sbias[r - c + SEQ - 2];
                    const float m0 = cell[0], m1 = cell[1];
                    cell[0] = acc[i][j][hh * 2 + 0] + m0 + b0;
                    cell[1] = acc[i][j][hh * 2 + 1] + m1 + b1;
                }
            }
        }
    }
    __syncthreads();

    // ---- Row softmax; writes P as tf32 bits ----
    {
        for (int r = wid; r < SEQ; r += 8) {
            float* row = sSf + r * AS_PITCH;
            float v0 = row[lane], v1 = row[lane + 32];
            float v2 = row[lane + 64], v3 = row[lane + 96];
            float mx = fmaxf(fmaxf(v0, v1), fmaxf(v2, v3));
            #pragma unroll
            for (int o = 16; o; o >>= 1) mx = fmaxf(mx, __shfl_xor_sync(0xffffffffu, mx, o));
            v0 = __expf(v0 - mx); v1 = __expf(v1 - mx);
            v2 = __expf(v2 - mx); v3 = __expf(v3 - mx);
            float s = v0 + v1 + v2 + v3;
            #pragma unroll
            for (int o = 16; o; o >>= 1) s += __shfl_xor_sync(0xffffffffu, s, o);
            const float inv = 1.0f / s;
            uint32_t* rowu = (uint32_t*)row;
            rowu[lane]      = f2tf32(v0 * inv);
            rowu[lane + 32] = f2tf32(v1 * inv);
            rowu[lane + 64] = f2tf32(v2 * inv);
            rowu[lane + 96] = f2tf32(v3 * inv);
        }
    }
    __syncthreads();

    // ---- out = P @ V (fp16 store) ----
    {
        const int wm = (wid & 3) * 32;
        const int wn = (wid >> 2) * 32;
        const uint32_t aB = sS_a + ((wm + a_lr) * AS_PITCH + a_lk) * 4u;
        float acc[2][4][4] = {};
        #pragma unroll 4
        for (int ks = 0; ks < SEQ; ks += 8) {
            uint32_t af[2][4], bf[4][2];
            #pragma unroll
            for (int i = 0; i < 2; i++)
                ldsm_x4(af[i], aB + (uint32_t)((i * 16 * AS_PITCH + ks) * 4));
            #pragma unroll
            for (int j = 0; j < 4; j++) {
                const int bb = (ks + t) * AQ_PITCH + wn + j * 8 + g;
                bf[j][0] = sv[bb];
                bf[j][1] = sv[bb + 4 * AQ_PITCH];
            }
            #pragma unroll
            for (int i = 0; i < 2; i++)
                #pragma unroll
                for (int j = 0; j < 4; j++)
                    mma_tf32(acc[i][j], af[i], bf[j]);
        }
        __half* obase = att + (size_t)b * SEQ * CDIM + h * HD;
        #pragma unroll
        for (int i = 0; i < 2; i++) {
            #pragma unroll
            for (int j = 0; j < 4; j++) {
                const int c = wn + j * 8 + t * 2;
                #pragma unroll
                for (int hh = 0; hh < 2; hh++) {
                    const int r = wm + i * 16 + g + hh * 8;
                    *(uint32_t*)(obase + (size_t)r * CDIM + c) =
                        pack_h2(acc[i][j][hh * 2 + 0], acc[i][j][hh * 2 + 1]);
                }
            }
        }
    }
}

// ---------------------------------------------------------------------------
// Launch
// ---------------------------------------------------------------------------
extern "C" void kernel_launch(void* const* d_in, const int* in_sizes, int n_in,
                              void* d_out, int out_size) {
    const float* x          = (const float*)d_in[0];
    const float* mask       = (const float*)d_in[1];
    const float* qkv_w      = (const float*)d_in[2];
    const float* bias_table = (const float*)d_in[3];
    const float* proj_w     = (const float*)d_in[4];
    const float* proj_b     = (const float*)d_in[5];
    float* out = (float*)d_out;

    __half* qkv; cudaGetSymbolAddress((void**)&qkv, g_qkv_h);
    __half* att; cudaGetSymbolAddress((void**)&att, g_att_h);
    __half* wh;  cudaGetSymbolAddress((void**)&wh, g_wh);

    cudaFuncSetAttribute(gemm_h2<false, true>,
                         cudaFuncAttributeMaxDynamicSharedMemorySize, GEMM_DSMEM);
    cudaFuncSetAttribute(gemm_h2<true, false>,
                         cudaFuncAttributeMaxDynamicSharedMemorySize, GEMM_DSMEM);
    cudaFuncSetAttribute(attn_kernel,
                         cudaFuncAttributeMaxDynamicSharedMemorySize, ATTN_SMEM_BYTES);

    // 0) Weight fp16 pre-convert
    cvt_weights<<<2304, 256>>>((const float4*)qkv_w, (const float4*)proj_w);

    // 1) QKV projection: qkv_h = x @ qkv_w^T  (A fp32 -> cvt, out fp16)
    gemm_h2<false, true><<<dim3(QKVDIM / 256, TOKENS / 128), 256, GEMM_DSMEM>>>(
        x, wh, nullptr, qkv, CDIM, QKVDIM);

    // 2) Fused attention per (b, h)  (tf32 mma core, fp16 I/O)
    attn_kernel<<<B_TOT * HEADS, 256, ATTN_SMEM_BYTES>>>(qkv, mask, bias_table, att);

    // 3) Output projection: out = att_h @ proj_w^T + proj_b  (A fp16 cp.async)
    gemm_h2<true, false><<<dim3(CDIM / 256, TOKENS / 128), 256, GEMM_DSMEM>>>(
        att, wh + (size_t)QKVDIM * CDIM, proj_b, out, CDIM, CDIM);
}

// round 17
// speedup vs baseline: 4.6129x; 1.1028x over previous
#include <cuda_runtime.h>
#include <cuda_fp16.h>
#include <cstdint>
#include <cstddef>

// Problem constants
#define B_TOT   256
#define SEQ     128
#define CDIM    768
#define HEADS   12
#define HD      64
#define NWN     64
#define TOKENS  (B_TOT * SEQ)          // 32768
#define QKVDIM  (3 * CDIM)             // 2304

// Scratch (allocation-free rule: __device__ globals) — fp16 intermediates
__device__ __half g_qkv_h[(size_t)TOKENS * QKVDIM];
__device__ __half g_att_h[(size_t)TOKENS * CDIM];
__device__ __half g_wh[(size_t)(QKVDIM + CDIM) * CDIM];   // qkv_w then proj_w

// ---------------------------------------------------------------------------
// Helpers
// ---------------------------------------------------------------------------
__device__ __forceinline__ uint32_t f2tf32(float x) {
    uint32_t r;
    asm("cvt.rna.tf32.f32 %0, %1;" : "=r"(r) : "f"(x));
    return r;
}
__device__ __forceinline__ uint32_t pack_h2(float lo, float hi) {
    __half2 h = __floats2half2_rn(lo, hi);
    return *reinterpret_cast<uint32_t*>(&h);
}

__device__ __forceinline__ void mma_tf32(float* c, const uint32_t* a, const uint32_t* b) {
    asm volatile("mma.sync.aligned.m16n8k8.row.col.f32.tf32.tf32.f32 "
        "{%0,%1,%2,%3}, {%4,%5,%6,%7}, {%8,%9}, {%0,%1,%2,%3};"
        : "+f"(c[0]), "+f"(c[1]), "+f"(c[2]), "+f"(c[3])
        : "r"(a[0]), "r"(a[1]), "r"(a[2]), "r"(a[3]), "r"(b[0]), "r"(b[1]));
}
__device__ __forceinline__ void mma_f16(float* c, const uint32_t* a, const uint32_t* b) {
    asm volatile("mma.sync.aligned.m16n8k16.row.col.f32.f16.f16.f32 "
        "{%0,%1,%2,%3}, {%4,%5,%6,%7}, {%8,%9}, {%0,%1,%2,%3};"
        : "+f"(c[0]), "+f"(c[1]), "+f"(c[2]), "+f"(c[3])
        : "r"(a[0]), "r"(a[1]), "r"(a[2]), "r"(a[3]), "r"(b[0]), "r"(b[1]));
}
__device__ __forceinline__ void ldsm_x4(uint32_t* r, uint32_t addr) {
    asm volatile("ldmatrix.sync.aligned.m8n8.x4.shared.b16 {%0,%1,%2,%3}, [%4];"
        : "=r"(r[0]), "=r"(r[1]), "=r"(r[2]), "=r"(r[3]) : "r"(addr));
}
__device__ __forceinline__ void cp16(uint32_t dst, const void* src) {
    asm volatile("cp.async.cg.shared.global [%0], [%1], 16;"
                 :: "r"(dst), "l"(src));
}
__device__ __forceinline__ void cp_commit() {
    asm volatile("cp.async.commit_group;");
}

// Per-lane offset pieces for ldmatrix fragment addressing.
#define A_LROW(lane) (((lane) & 7) + (((lane) >> 3) & 1) * 8)
#define A_LK(lane)   (((lane) >> 4) * 4)
#define B_LN(lane)   (((lane) & 7) + ((lane) >> 4) * 8)
#define B_LK(lane)   ((((lane) >> 3) & 1) * 4)

// ---------------------------------------------------------------------------
// Weight pre-convert: fp32 -> fp16 (qkv_w then proj_w), vectorized
// ---------------------------------------------------------------------------
__global__ void cvt_weights(const float4* __restrict__ qw,
                            const float4* __restrict__ pw) {
    const int n1 = (QKVDIM * CDIM) / 4;              // 442368
    const int nt = n1 + (CDIM * CDIM) / 4;           // 589824
    const int i = blockIdx.x * blockDim.x + threadIdx.x;
    if (i >= nt) return;
    float4 v = (i < n1) ? qw[i] : pw[i - n1];
    uint2 o;
    o.x = pack_h2(v.x, v.y);
    o.y = pack_h2(v.z, v.w);
    reinterpret_cast<uint2*>(g_wh)[i] = o;
}

// ---------------------------------------------------------------------------
// fp16 mma.sync GEMM: C[M,Nt] = A[M,K] @ W[Nt,K]^T (+bias), fp32 accum.
// CTA 128x256, 512 threads / 16 warps (2m x 8n), warp tile 64x32.
// K-chunk 32 (two k16 steps). B fp16 via cp.async; A fp32 LDG+cvt or fp16
// cp.async. GP 20 layout: ldmatrix 8-row phases tile all 32 banks.
// ---------------------------------------------------------------------------
#define GP 20
#define GEMM_DSMEM ((2 * 128 + 2 * 256) * GP * 4)    // 61440 B

template<bool A_HALF, bool OUT_HALF>
__global__ __launch_bounds__(512)
void gemm_h2(const void* __restrict__ Av, const __half* __restrict__ W,
             const float* __restrict__ bias, void* __restrict__ Cv,
             int K, int ldc) {
    extern __shared__ uint32_t dsm[];
    uint32_t* sA = dsm;                       // [2][128*GP]
    uint32_t* sB = dsm + 2 * 128 * GP;        // [2][256*GP]

    const int tid = threadIdx.x;
    const int bm = blockIdx.y * 128;
    const int bn = blockIdx.x * 256;
    const int nchunk = K / 32;

    const uint32_t sA_u = (uint32_t)__cvta_generic_to_shared(sA);
    const uint32_t sB_u = (uint32_t)__cvta_generic_to_shared(sB);

    // cp.async coords: 4 lanes per 64B fp16 row
    const int rB  = tid >> 2;                 // 0..127
    const int sg  = tid & 3;                  // 16B segment
    // A fp32 coords: 8 lanes per 128B row
    const int rA  = tid >> 3;                 // 0..63
    const int cA  = (tid & 7) * 4;

    const float* Af = (const float*)Av;
    const __half* Ah = (const __half*)Av;

    const int lane = tid & 31;
    const int g = lane >> 2;
    const int t = lane & 3;
    const int wid = tid >> 5;                 // 0..15
    const int wm = (wid & 1) * 64;
    const int wn = (wid >> 1) * 32;

    const uint32_t a_lr = A_LROW(lane), a_lk = A_LK(lane);
    const uint32_t b_ln = B_LN(lane),  b_lk = B_LK(lane);

    auto issue_cp = [&](int c) {
        const int s = c & 1;
        const int k0 = c * 32;
        #pragma unroll
        for (int p = 0; p < 2; p++) {
            const int r = rB + 128 * p;
            cp16(sB_u + (uint32_t)((((s * 256 + r) * GP) + sg * 4) * 4),
                 W + (size_t)(bn + r) * K + k0 + sg * 8);
        }
        if (A_HALF) {
            cp16(sA_u + (uint32_t)((((s * 128 + rB) * GP) + sg * 4) * 4),
                 Ah + (size_t)(bm + rB) * K + k0 + sg * 8);
        }
        cp_commit();
    };

    float4 fa[2];
    auto ldgA = [&](int c) {
        if (!A_HALF) {
            const int k0 = c * 32;
            #pragma unroll
            for (int p = 0; p < 2; p++)
                fa[p] = *(const float4*)(Af + (size_t)(bm + rA + 64 * p) * K + k0 + cA);
        }
    };
    auto stsA = [&](int s) {
        if (!A_HALF) {
            #pragma unroll
            for (int p = 0; p < 2; p++) {
                uint32_t* d = sA + (s * 128 + rA + 64 * p) * GP + (tid & 7) * 2;
                d[0] = pack_h2(fa[p].x, fa[p].y);
                d[1] = pack_h2(fa[p].z, fa[p].w);
            }
        }
    };

    float acc[4][4][4] = {};

    auto compute = [&](int s) {
        const uint32_t aB = sA_u + (uint32_t)((((s * 128 + wm + a_lr) * GP) + a_lk) * 4);
        const uint32_t bB = sB_u + (uint32_t)((((s * 256 + wn + b_ln) * GP) + b_lk) * 4);
        #pragma unroll
        for (int ks = 0; ks < 2; ks++) {
            uint32_t af[4][4], bf[4][2];
            #pragma unroll
            for (int i = 0; i < 4; i++)
                ldsm_x4(af[i], aB + (uint32_t)((i * 16 * GP + ks * 8) * 4));
            #pragma unroll
            for (int jj = 0; jj < 2; jj++) {
                uint32_t b4[4];
                ldsm_x4(b4, bB + (uint32_t)((jj * 16 * GP + ks * 8) * 4));
                bf[2 * jj][0] = b4[0]; bf[2 * jj][1] = b4[1];
                bf[2 * jj + 1][0] = b4[2]; bf[2 * jj + 1][1] = b4[3];
            }
            #pragma unroll
            for (int i = 0; i < 4; i++)
                #pragma unroll
                for (int j = 0; j < 4; j++)
                    mma_f16(acc[i][j], af[i], bf[j]);
        }
    };

    issue_cp(0);
    ldgA(0);
    #pragma unroll 1
    for (int c = 0; c < nchunk; ++c) {
        stsA(c & 1);
        if (c + 1 < nchunk) {
            issue_cp(c + 1);
            ldgA(c + 1);
            asm volatile("cp.async.wait_group 1;");
        } else {
            asm volatile("cp.async.wait_group 0;");
        }
        __syncthreads();
        compute(c & 1);
        if (c + 1 < nchunk) __syncthreads();
    }

    // Epilogue
    #pragma unroll
    for (int i = 0; i < 4; i++) {
        const int r0 = bm + wm + i * 16 + g;
        #pragma unroll
        for (int j = 0; j < 4; j++) {
            const int cl = bn + wn + j * 8 + t * 2;
            if (OUT_HALF) {
                __half* C = (__half*)Cv;
                *(uint32_t*)(C + (size_t)r0 * ldc + cl) =
                    pack_h2(acc[i][j][0], acc[i][j][1]);
                *(uint32_t*)(C + (size_t)(r0 + 8) * ldc + cl) =
                    pack_h2(acc[i][j][2], acc[i][j][3]);
            } else {
                float* C = (float*)Cv;
                float b0 = 0.f, b1 = 0.f;
                if (bias) { b0 = __ldg(bias + cl); b1 = __ldg(bias + cl + 1); }
                float2 v;
                v.x = acc[i][j][0] + b0; v.y = acc[i][j][1] + b1;
                *(float2*)(C + (size_t)r0 * ldc + cl) = v;
                v.x = acc[i][j][2] + b0; v.y = acc[i][j][3] + b1;
                *(float2*)(C + (size_t)(r0 + 8) * ldc + cl) = v;
            }
        }
    }
}

// ---------------------------------------------------------------------------
// Fused window attention: mma.sync tf32 core, fp16 gmem I/O.
// 512 threads / 16 warps. S: 4m x 4n warp grid (32x32). PV: 8m x 2n (16x32).
// ---------------------------------------------------------------------------
#define AQ_PITCH 68
#define AS_PITCH 132
#define ATTN_SMEM_WORDS (3 * 128 * AQ_PITCH + 128 * AS_PITCH + 256)
#define ATTN_SMEM_BYTES (ATTN_SMEM_WORDS * 4)

__global__ __launch_bounds__(512)
void attn_kernel(const __half* __restrict__ qkv, const float* __restrict__ mask,
                 const float* __restrict__ bias_table, __half* __restrict__ att) {
    extern __shared__ uint32_t smu[];
    uint32_t* sq   = smu;                       // [128][68] tf32
    uint32_t* sk   = smu + 128 * AQ_PITCH;      // [128][68] tf32
    uint32_t* sv   = smu + 2 * 128 * AQ_PITCH;  // [128][68] tf32
    uint32_t* sSu  = smu + 3 * 128 * AQ_PITCH;  // [128][132]
    float*    sSf  = (float*)sSu;
    float*    sbias = (float*)(sSu + 128 * AS_PITCH);  // [255]

    const int tid = threadIdx.x;
    const int lane = tid & 31;
    const int g = lane >> 2;
    const int t = lane & 3;
    const int wid = tid >> 5;                   // 0..15

    const int b = blockIdx.x / HEADS;
    const int h = blockIdx.x % HEADS;
    const int w = b & (NWN - 1);

    const __half* base = qkv + (size_t)b * SEQ * QKVDIM + h * HD;
    const float* mrow = mask + (size_t)w * (SEQ * SEQ);

    const uint32_t a_lr = A_LROW(lane), a_lk = A_LK(lane);
    const uint32_t b_ln = B_LN(lane),  b_lk = B_LK(lane);
    const uint32_t sq_a = (uint32_t)__cvta_generic_to_shared(sq);
    const uint32_t sk_a = (uint32_t)__cvta_generic_to_shared(sk);
    const uint32_t sS_a = (uint32_t)__cvta_generic_to_shared(sSu);

    // ---- Load q/k/v (fp16 gmem -> tf32 smem; q pre-scaled) ----
    for (int it = tid; it < SEQ * (HD / 4); it += 512) {
        const int r = it >> 4, c = (it & 15) * 4;
        const __half2* p = (const __half2*)(base + (size_t)r * QKVDIM + c);
        float2 q0 = __half22float2(p[0]),            q1 = __half22float2(p[1]);
        float2 k0 = __half22float2(p[CDIM / 2]),     k1 = __half22float2(p[CDIM / 2 + 1]);
        float2 v0 = __half22float2(p[CDIM]),         v1 = __half22float2(p[CDIM + 1]);
        uint32_t* dq = sq + r * AQ_PITCH + c;
        dq[0] = f2tf32(q0.x * 0.125f); dq[1] = f2tf32(q0.y * 0.125f);
        dq[2] = f2tf32(q1.x * 0.125f); dq[3] = f2tf32(q1.y * 0.125f);
        uint32_t* dk = sk + r * AQ_PITCH + c;
        dk[0] = f2tf32(k0.x); dk[1] = f2tf32(k0.y);
        dk[2] = f2tf32(k1.x); dk[3] = f2tf32(k1.y);
        uint32_t* dv = sv + r * AQ_PITCH + c;
        dv[0] = f2tf32(v0.x); dv[1] = f2tf32(v0.y);
        dv[2] = f2tf32(v1.x); dv[3] = f2tf32(v1.y);
    }
    for (int it = tid; it < SEQ * SEQ / 4; it += 512) {
        const int r = it >> 5, c = (it & 31) * 4;
        *(float4*)(sSf + r * AS_PITCH + c) = *(const float4*)(mrow + r * SEQ + c);
    }
    if (tid < 2 * SEQ - 1) sbias[tid] = bias_table[tid * HEADS + h];
    __syncthreads();

    // ---- S = q @ k^T  (warp tile 32m x 32n; 4m x 4n warp grid) ----
    {
        const int wm = (wid & 3) * 32;
        const int wn = (wid >> 2) * 32;
        const uint32_t aB = sq_a + ((wm + a_lr) * AQ_PITCH + a_lk) * 4u;
        const uint32_t bB = sk_a + ((wn + b_ln) * AQ_PITCH + b_lk) * 4u;
        float acc[2][4][4] = {};
        #pragma unroll
        for (int ks = 0; ks < HD; ks += 8) {
            uint32_t af[2][4], bf[4][2];
            #pragma unroll
            for (int i = 0; i < 2; i++)
                ldsm_x4(af[i], aB + (uint32_t)((i * 16 * AQ_PITCH + ks) * 4));
            #pragma unroll
            for (int j = 0; j < 4; j += 2) {
                uint32_t b4[4];
                ldsm_x4(b4, bB + (uint32_t)((j * 8 * AQ_PITCH + ks) * 4));
                bf[j][0] = b4[0]; bf[j][1] = b4[1];
                bf[j + 1][0] = b4[2]; bf[j + 1][1] = b4[3];
            }
            #pragma unroll
            for (int i = 0; i < 2; i++)
                #pragma unroll
                for (int j = 0; j < 4; j++)
                    mma_tf32(acc[i][j], af[i], bf[j]);
        }
        #pragma unroll
        for (int i = 0; i < 2; i++) {
            #pragma unroll
            for (int j = 0; j < 4; j++) {
                const int c = wn + j * 8 + t * 2;
                #pragma unroll
                for (int hh = 0; hh < 2; hh++) {
                    const int r = wm + i * 16 + g + hh * 8;
                    float* cell = sSf + r * AS_PITCH + c;
                    const float b0 = sbias[r - c + SEQ - 1];
                    const float b1 = sbias[r - c + SEQ - 2];
                    const float m0 = cell[0], m1 = cell[1];
                    cell[0] = acc[i][j][hh * 2 + 0] + m0 + b0;
                    cell[1] = acc[i][j][hh * 2 + 1] + m1 + b1;
                }
            }
        }
    }
    __syncthreads();

    // ---- Row softmax (16 warps, 8 rows each); writes P as tf32 bits ----
    {
        for (int r = wid; r < SEQ; r += 16) {
            float* row = sSf + r * AS_PITCH;
            float v0 = row[lane], v1 = row[lane + 32];
            float v2 = row[lane + 64], v3 = row[lane + 96];
            float mx = fmaxf(fmaxf(v0, v1), fmaxf(v2, v3));
            #pragma unroll
            for (int o = 16; o; o >>= 1) mx = fmaxf(mx, __shfl_xor_sync(0xffffffffu, mx, o));
            v0 = __expf(v0 - mx); v1 = __expf(v1 - mx);
            v2 = __expf(v2 - mx); v3 = __expf(v3 - mx);
            float s = v0 + v1 + v2 + v3;
            #pragma unroll
            for (int o = 16; o; o >>= 1) s += __shfl_xor_sync(0xffffffffu, s, o);
            const float inv = 1.0f / s;
            uint32_t* rowu = (uint32_t*)row;
            rowu[lane]      = f2tf32(v0 * inv);
            rowu[lane + 32] = f2tf32(v1 * inv);
            rowu[lane + 64] = f2tf32(v2 * inv);
            rowu[lane + 96] = f2tf32(v3 * inv);
        }
    }
    __syncthreads();

    // ---- out = P @ V  (warp tile 16m x 32n; 8m x 2n warp grid) ----
    {
        const int wm = (wid & 7) * 16;
        const int wn = (wid >> 3) * 32;
        const uint32_t aB = sS_a + ((wm + a_lr) * AS_PITCH + a_lk) * 4u;
        float acc[4][4] = {};
        #pragma unroll 4
        for (int ks = 0; ks < SEQ; ks += 8) {
            uint32_t af[4], bf[4][2];
            ldsm_x4(af, aB + (uint32_t)(ks * 4));
            #pragma unroll
            for (int j = 0; j < 4; j++) {
                const int bb = (ks + t) * AQ_PITCH + wn + j * 8 + g;
                bf[j][0] = sv[bb];
                bf[j][1] = sv[bb + 4 * AQ_PITCH];
            }
            #pragma unroll
            for (int j = 0; j < 4; j++)
                mma_tf32(acc[j], af, bf[j]);
        }
        __half* obase = att + (size_t)b * SEQ * CDIM + h * HD;
        #pragma unroll
        for (int j = 0; j < 4; j++) {
            const int c = wn + j * 8 + t * 2;
            #pragma unroll
            for (int hh = 0; hh < 2; hh++) {
                const int r = wm + g + hh * 8;
                *(uint32_t*)(obase + (size_t)r * CDIM + c) =
                    pack_h2(acc[j][hh * 2 + 0], acc[j][hh * 2 + 1]);
            }
        }
    }
}

// ---------------------------------------------------------------------------
// Launch
// ---------------------------------------------------------------------------
extern "C" void kernel_launch(void* const* d_in, const int* in_sizes, int n_in,
                              void* d_out, int out_size) {
    const float* x          = (const float*)d_in[0];
    const float* mask       = (const float*)d_in[1];
    const float* qkv_w      = (const float*)d_in[2];
    const float* bias_table = (const float*)d_in[3];
    const float* proj_w     = (const float*)d_in[4];
    const float* proj_b     = (const float*)d_in[5];
    float* out = (float*)d_out;

    __half* qkv; cudaGetSymbolAddress((void**)&qkv, g_qkv_h);
    __half* att; cudaGetSymbolAddress((void**)&att, g_att_h);
    __half* wh;  cudaGetSymbolAddress((void**)&wh, g_wh);

    cudaFuncSetAttribute(gemm_h2<false, true>,
                         cudaFuncAttributeMaxDynamicSharedMemorySize, GEMM_DSMEM);
    cudaFuncSetAttribute(gemm_h2<true, false>,
                         cudaFuncAttributeMaxDynamicSharedMemorySize, GEMM_DSMEM);
    cudaFuncSetAttribute(attn_kernel,
                         cudaFuncAttributeMaxDynamicSharedMemorySize, ATTN_SMEM_BYTES);

    // 0) Weight fp16 pre-convert
    cvt_weights<<<2304, 256>>>((const float4*)qkv_w, (const float4*)proj_w);

    // 1) QKV projection: qkv_h = x @ qkv_w^T  (A fp32 -> cvt, out fp16)
    gemm_h2<false, true><<<dim3(QKVDIM / 256, TOKENS / 128), 512, GEMM_DSMEM>>>(
        x, wh, nullptr, qkv, CDIM, QKVDIM);

    // 2) Fused attention per (b, h)  (tf32 mma core, fp16 I/O)
    attn_kernel<<<B_TOT * HEADS, 512, ATTN_SMEM_BYTES>>>(qkv, mask, bias_table, att);

    // 3) Output projection: out = att_h @ proj_w^T + proj_b  (A fp16 cp.async)
    gemm_h2<true, false><<<dim3(CDIM / 256, TOKENS / 128), 512, GEMM_DSMEM>>>(
        att, wh + (size_t)QKVDIM * CDIM, proj_b, out, CDIM, CDIM);
}